// round 8
// baseline (speedup 1.0000x reference)
#include <cuda_runtime.h>
#include <math.h>

// ---------------------------------------------------------------------------
// NNGAT_Net: B=512, N=200, INDIM=200.
// One CTA per batch, 512 threads (16 warps), 72.5KB smem, <=42 regs
// => 3 CTAs/SM (48 warps). Chunk-wise double-buffered alpha scratch (128
// floats/warp) replaces the 224-float rows; Phase A 4-row ILP.
// Output: logp [512*2] | s1 [512*100] | s2 [512*50]
// ---------------------------------------------------------------------------

namespace {
constexpr int N_    = 200;
constexpr int IND   = 200;
constexpr int D1_   = 32;
constexpr int D2_   = 32;
constexpr int K1_   = 100;
constexpr int K2_   = 50;
constexpr int NT    = 512;          // 16 warps
constexpr int NW    = 16;
constexpr int ALW   = 128;          // per-warp alpha scratch (4 x 32)
constexpr float NEGF = -1e9f;

// shared memory layout (float indices)
constexpr int OFF_H     = 0;        // 6400: h1 [200x32]; later xk[100x32], xk2[50x32]@+3200
constexpr int OFF_HO    = 6400;     // 6400: W1 staged -> hout1 [200x32] -> sH2/sOUT2
constexpr int OFF_AL    = 12800;    // 2048: per-warp alpha scratch [16x128]; readout scratch
constexpr int OFF_ES    = 14848;    // 200
constexpr int OFF_ED    = 15048;    // 200
constexpr int OFF_SC    = 15248;    // 200
constexpr int OFF_VAL   = 15448;    // 100
constexpr int OFF_PERM  = 15548;    // 100 (int)
constexpr int OFF_PERM2 = 15648;    // 52  (int)
constexpr int OFF_ADJB  = 15700;    // 1400 (u32): adj bitset [200][7]; later W2 [32x32]
constexpr int OFF_AKB   = 17100;    // 400 (u32)
constexpr int OFF_A2B   = 17500;    // 400 (u32)
constexpr int OFF_Z     = 17900;    // 192
constexpr int OFF_RED   = 18092;    // 32
constexpr int SMEM_FLOATS = 18124;  // 72496 bytes -> 3 CTAs/SM (217.5KB)
}

__device__ __forceinline__ float warpMax(float v) {
    #pragma unroll
    for (int o = 16; o > 0; o >>= 1) v = fmaxf(v, __shfl_xor_sync(0xffffffffu, v, o));
    return v;
}
__device__ __forceinline__ float warpSum(float v) {
    #pragma unroll
    for (int o = 16; o > 0; o >>= 1) v += __shfl_xor_sync(0xffffffffu, v, o);
    return v;
}
__device__ __forceinline__ float lrelu02(float x) { return x > 0.f ? x : 0.2f * x; }

__global__ __launch_bounds__(NT, 3)
void nngat_kernel(
    const float* __restrict__ x,     const float* __restrict__ adj,
    const float* __restrict__ W1,    const float* __restrict__ a1s,
    const float* __restrict__ a1d,   const float* __restrict__ b1,
    const float* __restrict__ W2,    const float* __restrict__ a2s,
    const float* __restrict__ a2d,   const float* __restrict__ b2,
    const float* __restrict__ pw1,   const float* __restrict__ pw2,
    const float* __restrict__ fc1_w, const float* __restrict__ fc1_b,
    const float* __restrict__ fc2_w, const float* __restrict__ fc2_b,
    const float* __restrict__ fc3_w, const float* __restrict__ fc3_b,
    const float* __restrict__ bn4_g, const float* __restrict__ bn4_b,
    const float* __restrict__ bn5_g, const float* __restrict__ bn5_b,
    float* __restrict__ out)
{
    extern __shared__ float sm[];
    int*      smi = (int*)sm;
    unsigned* smu = (unsigned*)sm;

    const int b    = blockIdx.x;
    const int tid  = threadIdx.x;
    const int lane = tid & 31;
    const int wid  = tid >> 5;

    const float* xb   = x   + (size_t)b * N_ * IND;
    const float* adjb = adj + (size_t)b * N_ * N_;

    // ---- stage W1 into (currently dead) HO region; pw norms ----
    {
        const float4* w4 = (const float4*)W1;
        float4* d4 = (float4*)(sm + OFF_HO);
        for (int t = tid; t < IND * D1_ / 4; t += NT) d4[t] = w4[t];
    }
    if (wid == 0) {
        float v = pw1[lane];
        float s = warpSum(v * v);
        if (lane == 0) sm[OFF_RED + 0] = sqrtf(s) + 1e-16f;
    }
    if (wid == 1) {
        float v = pw2[lane];
        float s = warpSum(v * v);
        if (lane == 0) sm[OFF_RED + 1] = sqrtf(s) + 1e-16f;
    }
    __syncthreads();

    const float a1s_l = __ldg(&a1s[lane]);
    const float a1d_l = __ldg(&a1d[lane]);
    const float b1_l  = __ldg(&b1[lane]);

    // ============ Phase A: h = x @ W1 ; es/ed (4-row groups) ================
    {
        const float* sW = sm + OFF_HO;
        for (int g = wid; g < 50; g += NW) {
            const int ib = g * 4;
            const float4* xp0 = (const float4*)(xb + (ib + 0) * IND);
            const float4* xp1 = (const float4*)(xb + (ib + 1) * IND);
            const float4* xp2 = (const float4*)(xb + (ib + 2) * IND);
            const float4* xp3 = (const float4*)(xb + (ib + 3) * IND);
            float a0 = 0.f, a1 = 0.f, a2 = 0.f, a3 = 0.f;
            for (int k4 = 0; k4 < IND / 4; k4++) {
                float4 v0 = __ldg(xp0 + k4);
                float4 v1 = __ldg(xp1 + k4);
                float4 v2 = __ldg(xp2 + k4);
                float4 v3 = __ldg(xp3 + k4);
                const int k = k4 * 4;
                float w0 = sW[(k + 0) * D1_ + lane];
                float w1 = sW[(k + 1) * D1_ + lane];
                float w2 = sW[(k + 2) * D1_ + lane];
                float w3 = sW[(k + 3) * D1_ + lane];
                a0 = fmaf(v0.x, w0, fmaf(v0.y, w1, fmaf(v0.z, w2, fmaf(v0.w, w3, a0))));
                a1 = fmaf(v1.x, w0, fmaf(v1.y, w1, fmaf(v1.z, w2, fmaf(v1.w, w3, a1))));
                a2 = fmaf(v2.x, w0, fmaf(v2.y, w1, fmaf(v2.z, w2, fmaf(v2.w, w3, a2))));
                a3 = fmaf(v3.x, w0, fmaf(v3.y, w1, fmaf(v3.z, w2, fmaf(v3.w, w3, a3))));
            }
            float hr[4] = {a0, a1, a2, a3};
            #pragma unroll
            for (int r = 0; r < 4; r++) {
                sm[OFF_H + (ib + r) * D1_ + lane] = hr[r];
                float es = warpSum(hr[r] * a1s_l);
                float ed = warpSum(hr[r] * a1d_l);
                if (lane == 0) { sm[OFF_ES + ib + r] = es; sm[OFF_ED + ib + r] = ed; }
            }
        }
    }
    __syncthreads();   // W1 staging dead; HO becomes hout1

    // ============ Phase B: GAT1 softmax + sparse agg (chunk scratch) ========
    {
        float* al = sm + OFF_AL + wid * ALW;   // double-buffered 32-float slots
        for (int i = wid; i < N_; i += NW) {
            float wv[7];
            #pragma unroll
            for (int c = 0; c < 7; c++) {
                const int j = c * 32 + lane;
                wv[c] = (j < N_) ? adjb[i * N_ + j] : 0.f;
            }

            const float edi = sm[OFF_ED + i];
            unsigned mw[7];
            float alr[7];
            float mx = -INFINITY;
            #pragma unroll
            for (int c = 0; c < 7; c++) {
                const int j = c * 32 + lane;
                unsigned bal = __ballot_sync(0xffffffffu, wv[c] > 0.f);
                if (lane == 0) smu[OFF_ADJB + i * 7 + c] = bal;  // pure adjacency
                if ((i >> 5) == c) bal |= 1u << (i & 31);        // self-loop
                mw[c] = bal;
                float lg = NEGF;
                if ((bal >> lane) & 1u) lg = lrelu02(edi + sm[OFF_ES + j]);
                alr[c] = lg;
                mx = fmaxf(mx, lg);
            }
            mx = warpMax(mx);

            float s = 0.f;
            #pragma unroll
            for (int c = 0; c < 7; c++) {
                float e = __expf(alr[c] - mx);    // masked lanes underflow to 0
                alr[c] = e;
                s += e;
            }
            s = warpSum(s);
            const float inv = __fdividef(1.f, s);

            __syncwarp();   // prior row's buffer-0 reads done before overwrite
            float acc0 = 0.f, acc1 = 0.f, acc2 = 0.f, acc3 = 0.f;
            #pragma unroll
            for (int c = 0; c < 7; c++) {
                float* ab = al + (c & 1) * 32;
                ab[lane] = alr[c];
                __syncwarp();
                unsigned w = mw[c];               // warp-uniform
                const float* hb = sm + OFF_H + c * 32 * D1_ + lane;
                while (w) {
                    const int t0 = __ffs(w) - 1; w &= w - 1;
                    acc0 = fmaf(ab[t0], hb[t0 * D1_], acc0);
                    if (!w) break;
                    const int t1 = __ffs(w) - 1; w &= w - 1;
                    acc1 = fmaf(ab[t1], hb[t1 * D1_], acc1);
                    if (!w) break;
                    const int t2 = __ffs(w) - 1; w &= w - 1;
                    acc2 = fmaf(ab[t2], hb[t2 * D1_], acc2);
                    if (!w) break;
                    const int t3 = __ffs(w) - 1; w &= w - 1;
                    acc3 = fmaf(ab[t3], hb[t3 * D1_], acc3);
                }
            }
            sm[OFF_HO + i * D1_ + lane] = ((acc0 + acc1) + (acc2 + acc3)) * inv + b1_l;
        }
    }
    __syncthreads();

    // ============ Phase C: pool-1 scores ====================================
    {
        const float pw1_l = __ldg(&pw1[lane]);
        const float invn1 = __fdividef(1.f, sm[OFF_RED + 0]);
        for (int i = wid; i < N_; i += NW) {
            float s = warpSum(sm[OFF_HO + i * D1_ + lane] * pw1_l);
            if (lane == 0) sm[OFF_SC + i] = __fdividef(1.f, 1.f + __expf(-s * invn1));
        }
    }
    __syncthreads();

    // stable descending rank == jax.lax.top_k order
    if (tid < N_) {
        const float si = sm[OFF_SC + tid];
        int cnt = 0;
        for (int j = 0; j < N_; j++) {
            const float sj = sm[OFF_SC + j];
            cnt += (sj > si) || (sj == si && j < tid);
        }
        if (cnt < K1_) smi[OFF_PERM + cnt] = tid;
    }
    __syncthreads();

    for (int r = tid; r < K1_; r += NT) {
        float v = sm[OFF_SC + smi[OFF_PERM + r]];
        sm[OFF_VAL + r] = v;
        out[512 * 2 + (size_t)b * K1_ + r] = v;
    }
    __syncthreads();

    // gated xk = hout[perm] * vals  (into dead h1 region)
    for (int t = tid; t < K1_ * D1_; t += NT) {
        const int r = t >> 5, d = t & 31;
        sm[OFF_H + t] = sm[OFF_HO + smi[OFF_PERM + r] * D1_ + d] * sm[OFF_VAL + r];
    }
    __syncthreads();

    // x1 readout partials (warps 0-3)
    if (wid < 4) {
        float mx = -INFINITY, s = 0.f;
        for (int r = wid * 25; r < wid * 25 + 25; r++) {
            float v = sm[OFF_H + r * D1_ + lane];
            mx = fmaxf(mx, v);
            s += v;
        }
        sm[OFF_AL + (wid * 2 + 0) * 32 + lane] = mx;
        sm[OFF_AL + (wid * 2 + 1) * 32 + lane] = s;
    }
    // AKB via warp ballot: lane = pooled column
    for (int r = wid; r < K1_; r += NW) {
        const int pr = smi[OFF_PERM + r];
        const unsigned* arow = smu + OFF_ADJB + pr * 7;
        #pragma unroll
        for (int w = 0; w < 4; w++) {
            const int c = w * 32 + lane;
            bool bit = false;
            if (c < K1_) {
                const int pc = smi[OFF_PERM + c];
                bit = (arow[pc >> 5] >> (pc & 31)) & 1u;
            }
            unsigned bal = __ballot_sync(0xffffffffu, bit);
            if (lane == 0) smu[OFF_AKB + r * 4 + w] = bal;
        }
    }
    __syncthreads();   // ADJB dead from here

    // combine x1 partials; a2 = ak | (ak_nz @ ak_nz); stage W2 into ADJB
    if (tid < 32) {
        float mx = fmaxf(fmaxf(sm[OFF_AL + 0 * 32 + lane], sm[OFF_AL + 2 * 32 + lane]),
                         fmaxf(sm[OFF_AL + 4 * 32 + lane], sm[OFF_AL + 6 * 32 + lane]));
        float s = sm[OFF_AL + 1 * 32 + lane] + sm[OFF_AL + 3 * 32 + lane]
                + sm[OFF_AL + 5 * 32 + lane] + sm[OFF_AL + 7 * 32 + lane];
        sm[OFF_Z + lane]      = mx;
        sm[OFF_Z + 32 + lane] = s * (1.f / K1_);
    }
    for (int t = tid; t < K1_ * 4; t += NT) {
        const int r = t >> 2, w = t & 3;
        unsigned acc = smu[OFF_AKB + t];
        #pragma unroll
        for (int kc = 0; kc < 4; kc++) {
            unsigned rw = smu[OFF_AKB + r * 4 + kc];
            while (rw) {
                const int k = __ffs(rw) - 1; rw &= rw - 1;
                acc |= smu[OFF_AKB + (kc * 32 + k) * 4 + w];
            }
        }
        smu[OFF_A2B + t] = acc;
    }
    for (int t = tid; t < D1_ * D2_; t += NT) sm[OFF_ADJB + t] = W2[t];
    __syncthreads();

    // ============ Phase E: GAT2 =============================================
    const float a2s_l = __ldg(&a2s[lane]);
    const float a2d_l = __ldg(&a2d[lane]);
    const float b2_l  = __ldg(&b2[lane]);
    float* sXK   = sm + OFF_H;                 // [100x32]
    float* sH2   = sm + OFF_HO;                // [100x32]
    float* sOUT2 = sm + OFF_HO + K1_ * D2_;    // [100x32]
    float* sW2   = sm + OFF_ADJB;              // [32x32]

    for (int i = wid; i < K1_; i += NW) {
        const float4* xr4 = (const float4*)(sXK + i * D1_);
        float acc = 0.f;
        #pragma unroll
        for (int k4 = 0; k4 < D1_ / 4; k4++) {
            float4 xv = xr4[k4];
            const int k = k4 * 4;
            acc = fmaf(xv.x, sW2[(k + 0) * D2_ + lane], acc);
            acc = fmaf(xv.y, sW2[(k + 1) * D2_ + lane], acc);
            acc = fmaf(xv.z, sW2[(k + 2) * D2_ + lane], acc);
            acc = fmaf(xv.w, sW2[(k + 3) * D2_ + lane], acc);
        }
        sH2[i * D2_ + lane] = acc;
        float es = warpSum(acc * a2s_l);
        float ed = warpSum(acc * a2d_l);
        if (lane == 0) { sm[OFF_ES + i] = es; sm[OFF_ED + i] = ed; }
    }
    __syncthreads();

    // GAT2 attention + aggregation: 2 rows per warp, chunk-wise scratch
    for (int g = wid; g < K1_ / 2; g += NW) {
        const int i0 = 2 * g, i1 = i0 + 1;
        const float ed0 = sm[OFF_ED + i0];
        const float ed1 = sm[OFF_ED + i1];
        float* al2 = sm + OFF_AL + wid * ALW;  // 4 x 32 slots
        float er0[4], er1[4];
        float mx0 = -INFINITY, mx1 = -INFINITY;
        #pragma unroll
        for (int c = 0; c < 4; c++) {
            const int j = c * 32 + lane;
            float lg0 = NEGF, lg1 = NEGF;
            if (j < K1_) {
                const float esj = sm[OFF_ES + j];
                const unsigned b0 = smu[OFF_A2B + i0 * 4 + c];
                const unsigned b1w = smu[OFF_A2B + i1 * 4 + c];
                if ((j == i0) || ((b0 >> lane) & 1u))  lg0 = lrelu02(ed0 + esj);
                if ((j == i1) || ((b1w >> lane) & 1u)) lg1 = lrelu02(ed1 + esj);
            }
            er0[c] = lg0; er1[c] = lg1;
            mx0 = fmaxf(mx0, lg0); mx1 = fmaxf(mx1, lg1);
        }
        mx0 = warpMax(mx0); mx1 = warpMax(mx1);
        float s0 = 0.f, s1 = 0.f;
        #pragma unroll
        for (int c = 0; c < 4; c++) {
            float e0 = __expf(er0[c] - mx0);   // j>=K1 lanes -> 0
            float e1 = __expf(er1[c] - mx1);
            er0[c] = e0; er1[c] = e1;
            s0 += e0; s1 += e1;
        }
        s0 = warpSum(s0); s1 = warpSum(s1);
        const float inv0 = __fdividef(1.f, s0);
        const float inv1 = __fdividef(1.f, s1);

        __syncwarp();   // prior iteration's buffer reads done
        float p00 = 0.f, p01 = 0.f, p02 = 0.f, p03 = 0.f;
        float p10 = 0.f, p11 = 0.f, p12 = 0.f, p13 = 0.f;
        #pragma unroll
        for (int c = 0; c < 4; c++) {
            float* b0p = al2 + ((c & 1) * 2 + 0) * 32;
            float* b1p = al2 + ((c & 1) * 2 + 1) * 32;
            b0p[lane] = er0[c];
            b1p[lane] = er1[c];
            __syncwarp();
            const int jn4 = (c < 3) ? 8 : 1;   // chunk widths 32,32,32,4
            const float4* a40 = (const float4*)b0p;
            const float4* a41 = (const float4*)b1p;
            const float* hbase = sH2 + c * 32 * D2_ + lane;
            #pragma unroll
            for (int j4 = 0; j4 < 8; j4++) {
                if (j4 >= jn4) break;
                float4 a0 = a40[j4];
                float4 a1 = a41[j4];
                const float* hp = hbase + j4 * 4 * D2_;
                float h0 = hp[0 * D2_];
                float h1 = hp[1 * D2_];
                float h2 = hp[2 * D2_];
                float h3 = hp[3 * D2_];
                p00 = fmaf(a0.x, h0, p00); p01 = fmaf(a0.y, h1, p01);
                p02 = fmaf(a0.z, h2, p02); p03 = fmaf(a0.w, h3, p03);
                p10 = fmaf(a1.x, h0, p10); p11 = fmaf(a1.y, h1, p11);
                p12 = fmaf(a1.z, h2, p12); p13 = fmaf(a1.w, h3, p13);
            }
        }
        sOUT2[i0 * D2_ + lane] = ((p00 + p01) + (p02 + p03)) * inv0 + b2_l;
        sOUT2[i1 * D2_ + lane] = ((p10 + p11) + (p12 + p13)) * inv1 + b2_l;
    }
    __syncthreads();

    // ============ Phase F: pool-2 ===========================================
    {
        const float pw2_l = __ldg(&pw2[lane]);
        const float invn2 = __fdividef(1.f, sm[OFF_RED + 1]);
        for (int i = wid; i < K1_; i += NW) {
            float s = warpSum(sOUT2[i * D2_ + lane] * pw2_l);
            if (lane == 0) sm[OFF_SC + i] = __fdividef(1.f, 1.f + __expf(-s * invn2));
        }
    }
    __syncthreads();

    if (tid < K1_) {
        const float si = sm[OFF_SC + tid];
        int cnt = 0;
        for (int j = 0; j < K1_; j++) {
            const float sj = sm[OFF_SC + j];
            cnt += (sj > si) || (sj == si && j < tid);
        }
        if (cnt < K2_) smi[OFF_PERM2 + cnt] = tid;
    }
    __syncthreads();

    for (int r = tid; r < K2_; r += NT) {
        float v = sm[OFF_SC + smi[OFF_PERM2 + r]];
        sm[OFF_VAL + r] = v;
        out[512 * 2 + 512 * K1_ + (size_t)b * K2_ + r] = v;
    }
    __syncthreads();

    float* sXK2 = sm + OFF_H + K1_ * D1_;   // [50x32]
    for (int t = tid; t < K2_ * D2_; t += NT) {
        const int r = t >> 5, d = t & 31;
        sXK2[t] = sOUT2[smi[OFF_PERM2 + r] * D2_ + d] * sm[OFF_VAL + r];
    }
    __syncthreads();

    // x2 readout partials (warps 0-1)
    if (wid < 2) {
        float mx = -INFINITY, s = 0.f;
        for (int r = wid * 25; r < wid * 25 + 25; r++) {
            float v = sXK2[r * D2_ + lane];
            mx = fmaxf(mx, v);
            s += v;
        }
        sm[OFF_AL + (wid * 2 + 0) * 32 + lane] = mx;
        sm[OFF_AL + (wid * 2 + 1) * 32 + lane] = s;
    }
    __syncthreads();
    if (tid < 32) {
        float mx = fmaxf(sm[OFF_AL + 0 * 32 + lane], sm[OFF_AL + 2 * 32 + lane]);
        float s  = sm[OFF_AL + 1 * 32 + lane] + sm[OFF_AL + 3 * 32 + lane];
        sm[OFF_Z + 64 + lane] = mx;
        sm[OFF_Z + 96 + lane] = s * (1.f / K2_);
    }
    __syncthreads();

    // ============ Phase G: MLP head (warp 0) ================================
    if (wid == 0) {
        const float invbn = 1.0f / sqrtf(1.0f + 1e-5f);
        float acc = __ldg(&fc1_b[lane]);
        #pragma unroll 4
        for (int k = 0; k < 128; k++) acc = fmaf(sm[OFF_Z + k], __ldg(&fc1_w[k * 32 + lane]), acc);
        acc = fmaxf(acc, 0.f);
        sm[OFF_Z + 128 + lane] = __ldg(&bn4_g[lane]) * acc * invbn + __ldg(&bn4_b[lane]);
        __syncwarp();
        if (lane < 8) {
            float a = __ldg(&fc2_b[lane]);
            #pragma unroll
            for (int k = 0; k < 32; k++) a = fmaf(sm[OFF_Z + 128 + k], __ldg(&fc2_w[k * 8 + lane]), a);
            a = fmaxf(a, 0.f);
            sm[OFF_Z + 160 + lane] = __ldg(&bn5_g[lane]) * a * invbn + __ldg(&bn5_b[lane]);
        }
        __syncwarp();
        if (lane < 2) {
            float a = __ldg(&fc3_b[lane]);
            #pragma unroll
            for (int k = 0; k < 8; k++) a = fmaf(sm[OFF_Z + 160 + k], __ldg(&fc3_w[k * 2 + lane]), a);
            sm[OFF_Z + 170 + lane] = a;
        }
        __syncwarp();
        if (lane == 0) {
            float l0 = sm[OFF_Z + 170], l1 = sm[OFF_Z + 171];
            float m = fmaxf(l0, l1);
            float lse = m + __logf(__expf(l0 - m) + __expf(l1 - m));
            out[(size_t)b * 2 + 0] = l0 - lse;
            out[(size_t)b * 2 + 1] = l1 - lse;
        }
    }
}

extern "C" void kernel_launch(void* const* d_in, const int* in_sizes, int n_in,
                              void* d_out, int out_size) {
    const float* x     = (const float*)d_in[0];
    const float* adj   = (const float*)d_in[1];
    const float* W1    = (const float*)d_in[2];
    const float* a1s   = (const float*)d_in[3];
    const float* a1d   = (const float*)d_in[4];
    const float* b1    = (const float*)d_in[5];
    const float* W2    = (const float*)d_in[6];
    const float* a2s   = (const float*)d_in[7];
    const float* a2d   = (const float*)d_in[8];
    const float* b2    = (const float*)d_in[9];
    const float* pw1   = (const float*)d_in[10];
    const float* pw2   = (const float*)d_in[11];
    const float* fc1w  = (const float*)d_in[12];
    const float* fc1b  = (const float*)d_in[13];
    const float* fc2w  = (const float*)d_in[14];
    const float* fc2b  = (const float*)d_in[15];
    const float* fc3w  = (const float*)d_in[16];
    const float* fc3b  = (const float*)d_in[17];
    const float* bn4g  = (const float*)d_in[18];
    const float* bn4b  = (const float*)d_in[19];
    const float* bn5g  = (const float*)d_in[20];
    const float* bn5b  = (const float*)d_in[21];
    float* out = (float*)d_out;

    const int smem_bytes = SMEM_FLOATS * (int)sizeof(float);
    cudaFuncSetAttribute(nngat_kernel, cudaFuncAttributeMaxDynamicSharedMemorySize,
                         smem_bytes);

    nngat_kernel<<<512, NT, smem_bytes>>>(
        x, adj, W1, a1s, a1d, b1, W2, a2s, a2d, b2, pw1, pw2,
        fc1w, fc1b, fc2w, fc2b, fc3w, fc3b, bn4g, bn4b, bn5g, bn5b, out);
}

// round 9
// speedup vs baseline: 1.0694x; 1.0694x over previous
#include <cuda_runtime.h>
#include <math.h>

// ---------------------------------------------------------------------------
// NNGAT_Net, 3-kernel pipeline:
//  k_h   : h = x@W1 (+es/ed) streamed at full-chip parallelism -> g_h/g_es/g_ed
//  k_adj : adjacency > 0 compressed to bitsets -> g_adjb
//  main  : per-batch GAT1-softmax/agg -> topk -> GAT2 -> topk -> MLP
//          (round-7 body: 512 thr, 78.6KB smem, 2 CTAs/SM, 64 regs)
// Output: logp [512*2] | s1 [512*100] | s2 [512*50]
// ---------------------------------------------------------------------------

namespace {
constexpr int B_    = 512;
constexpr int N_    = 200;
constexpr int IND   = 200;
constexpr int D1_   = 32;
constexpr int D2_   = 32;
constexpr int K1_   = 100;
constexpr int K2_   = 50;
constexpr int NT    = 512;          // main kernel: 16 warps
constexpr int NW    = 16;
constexpr int ALP   = 224;          // padded alpha row (7*32)
constexpr float NEGF = -1e9f;

// main-kernel shared memory layout (float indices) — round-7 layout
constexpr int OFF_H     = 0;        // 6400: h1 [200x32]; later xk[100x32], xk2[50x32]@+3200
constexpr int OFF_HO    = 6400;     // 6400: hout1 [200x32] -> sH2/sOUT2
constexpr int OFF_AL    = 12800;    // 3584: per-warp alpha rows [16x224]; readout scratch
constexpr int OFF_ES    = 16384;    // 200
constexpr int OFF_ED    = 16584;    // 200
constexpr int OFF_SC    = 16784;    // 200
constexpr int OFF_VAL   = 16984;    // 100
constexpr int OFF_PERM  = 17084;    // 100 (int)
constexpr int OFF_PERM2 = 17184;    // 52  (int)
constexpr int OFF_ADJB  = 17236;    // 1400 (u32): adj bitset [200][7]; later W2 [32x32]
constexpr int OFF_AKB   = 18636;    // 400 (u32)
constexpr int OFF_A2B   = 19036;    // 400 (u32)
constexpr int OFF_Z     = 19436;    // 192
constexpr int OFF_RED   = 19628;    // 32
constexpr int SMEM_FLOATS = 19660;  // 78640 bytes -> 2 CTAs/SM
}

// inter-kernel staging buffers (static device globals: allowed scratch)
__device__ float    g_h[(size_t)B_ * N_ * D1_];   // 13.1 MB
__device__ float    g_es[(size_t)B_ * N_];
__device__ float    g_ed[(size_t)B_ * N_];
__device__ unsigned g_adjb[(size_t)B_ * N_ * 7];  // 2.87 MB

__device__ __forceinline__ float warpMax(float v) {
    #pragma unroll
    for (int o = 16; o > 0; o >>= 1) v = fmaxf(v, __shfl_xor_sync(0xffffffffu, v, o));
    return v;
}
__device__ __forceinline__ float warpSum(float v) {
    #pragma unroll
    for (int o = 16; o > 0; o >>= 1) v += __shfl_xor_sync(0xffffffffu, v, o);
    return v;
}
__device__ __forceinline__ float lrelu02(float x) { return x > 0.f ? x : 0.2f * x; }

// ============ k_h: h = x @ W1 ; es = h.a1s ; ed = h.a1d =====================
// grid (512, 5), 256 threads (8 warps). Warp handles 5 consecutive rows.
__global__ __launch_bounds__(256)
void k_h(const float* __restrict__ x, const float* __restrict__ W1,
         const float* __restrict__ a1s, const float* __restrict__ a1d)
{
    __shared__ float sW[IND * D1_];
    const int b    = blockIdx.x;
    const int tid  = threadIdx.x;
    const int lane = tid & 31;
    const int wid  = tid >> 5;

    {
        const float4* w4 = (const float4*)W1;
        float4* d4 = (float4*)sW;
        for (int t = tid; t < IND * D1_ / 4; t += 256) d4[t] = w4[t];
    }
    __syncthreads();

    const float a1s_l = __ldg(&a1s[lane]);
    const float a1d_l = __ldg(&a1d[lane]);
    const float* xb = x + (size_t)b * N_ * IND;
    const int ib = blockIdx.y * 40 + wid * 5;

    const float4* xp0 = (const float4*)(xb + (ib + 0) * IND);
    const float4* xp1 = (const float4*)(xb + (ib + 1) * IND);
    const float4* xp2 = (const float4*)(xb + (ib + 2) * IND);
    const float4* xp3 = (const float4*)(xb + (ib + 3) * IND);
    const float4* xp4 = (const float4*)(xb + (ib + 4) * IND);
    float a0 = 0.f, a1 = 0.f, a2 = 0.f, a3 = 0.f, a4 = 0.f;
    #pragma unroll 2
    for (int k4 = 0; k4 < IND / 4; k4++) {
        float4 v0 = __ldg(xp0 + k4);
        float4 v1 = __ldg(xp1 + k4);
        float4 v2 = __ldg(xp2 + k4);
        float4 v3 = __ldg(xp3 + k4);
        float4 v4 = __ldg(xp4 + k4);
        const int k = k4 * 4;
        float w0 = sW[(k + 0) * D1_ + lane];
        float w1 = sW[(k + 1) * D1_ + lane];
        float w2 = sW[(k + 2) * D1_ + lane];
        float w3 = sW[(k + 3) * D1_ + lane];
        a0 = fmaf(v0.x, w0, fmaf(v0.y, w1, fmaf(v0.z, w2, fmaf(v0.w, w3, a0))));
        a1 = fmaf(v1.x, w0, fmaf(v1.y, w1, fmaf(v1.z, w2, fmaf(v1.w, w3, a1))));
        a2 = fmaf(v2.x, w0, fmaf(v2.y, w1, fmaf(v2.z, w2, fmaf(v2.w, w3, a2))));
        a3 = fmaf(v3.x, w0, fmaf(v3.y, w1, fmaf(v3.z, w2, fmaf(v3.w, w3, a3))));
        a4 = fmaf(v4.x, w0, fmaf(v4.y, w1, fmaf(v4.z, w2, fmaf(v4.w, w3, a4))));
    }
    float hr[5] = {a0, a1, a2, a3, a4};
    #pragma unroll
    for (int r = 0; r < 5; r++) {
        const size_t row = (size_t)b * N_ + (ib + r);
        g_h[row * D1_ + lane] = hr[r];
        float es = warpSum(hr[r] * a1s_l);
        float ed = warpSum(hr[r] * a1d_l);
        if (lane == 0) { g_es[row] = es; g_ed[row] = ed; }
    }
}

// ============ k_adj: adjacency > 0 -> bitsets ===============================
// grid 512, 256 threads (8 warps); warp handles rows wid, wid+8, ...
__global__ __launch_bounds__(256)
void k_adj(const float* __restrict__ adj)
{
    const int b    = blockIdx.x;
    const int lane = threadIdx.x & 31;
    const int wid  = threadIdx.x >> 5;
    const float* adjb = adj + (size_t)b * N_ * N_;

    for (int i = wid; i < N_; i += 8) {
        #pragma unroll
        for (int c = 0; c < 7; c++) {
            const int j = c * 32 + lane;
            float w = (j < N_) ? adjb[i * N_ + j] : 0.f;
            unsigned bal = __ballot_sync(0xffffffffu, w > 0.f);
            if (lane == 0) g_adjb[((size_t)b * N_ + i) * 7 + c] = bal;
        }
    }
}

// ============ main kernel ===================================================
__global__ __launch_bounds__(NT, 2)
void nngat_main(
    const float* __restrict__ W2,    const float* __restrict__ a2s,
    const float* __restrict__ a2d,   const float* __restrict__ b1,
    const float* __restrict__ b2,
    const float* __restrict__ pw1,   const float* __restrict__ pw2,
    const float* __restrict__ fc1_w, const float* __restrict__ fc1_b,
    const float* __restrict__ fc2_w, const float* __restrict__ fc2_b,
    const float* __restrict__ fc3_w, const float* __restrict__ fc3_b,
    const float* __restrict__ bn4_g, const float* __restrict__ bn4_b,
    const float* __restrict__ bn5_g, const float* __restrict__ bn5_b,
    float* __restrict__ out)
{
    extern __shared__ float sm[];
    int*      smi = (int*)sm;
    unsigned* smu = (unsigned*)sm;

    const int b    = blockIdx.x;
    const int tid  = threadIdx.x;
    const int lane = tid & 31;
    const int wid  = tid >> 5;

    // ---- stage h, es/ed, adj bitsets from the pre-kernels; pw norms ----
    {
        const float4* h4 = (const float4*)(g_h + (size_t)b * N_ * D1_);
        float4* d4 = (float4*)(sm + OFF_H);
        for (int t = tid; t < N_ * D1_ / 4; t += NT) d4[t] = h4[t];
    }
    for (int t = tid; t < N_; t += NT) {
        sm[OFF_ES + t] = g_es[(size_t)b * N_ + t];
        sm[OFF_ED + t] = g_ed[(size_t)b * N_ + t];
    }
    for (int t = tid; t < N_ * 7; t += NT)
        smu[OFF_ADJB + t] = g_adjb[(size_t)b * N_ * 7 + t];
    if (wid == 0) {
        float v = pw1[lane];
        float s = warpSum(v * v);
        if (lane == 0) sm[OFF_RED + 0] = sqrtf(s) + 1e-16f;
    }
    if (wid == 1) {
        float v = pw2[lane];
        float s = warpSum(v * v);
        if (lane == 0) sm[OFF_RED + 1] = sqrtf(s) + 1e-16f;
    }
    __syncthreads();

    const float b1_l = __ldg(&b1[lane]);

    // ============ Phase B: GAT1 softmax + sparse agg (bitsets in smem) ======
    {
        float* al = sm + OFF_AL + wid * ALP;
        for (int i = wid; i < N_; i += NW) {
            const float edi = sm[OFF_ED + i];
            unsigned mw[7];
            float alr[7];
            float mx = -INFINITY;
            #pragma unroll
            for (int c = 0; c < 7; c++) {
                unsigned bal = smu[OFF_ADJB + i * 7 + c];
                if ((i >> 5) == c) bal |= 1u << (i & 31);   // self-loop
                mw[c] = bal;
                float lg = NEGF;
                const int j = c * 32 + lane;
                if ((bal >> lane) & 1u) lg = lrelu02(edi + sm[OFF_ES + j]);
                alr[c] = lg;
                mx = fmaxf(mx, lg);
            }
            mx = warpMax(mx);

            float s = 0.f;
            #pragma unroll
            for (int c = 0; c < 7; c++) {
                float e = __expf(alr[c] - mx);    // masked lanes underflow to 0
                al[c * 32 + lane] = e;            // padded row: in-bounds
                s += e;
            }
            s = warpSum(s);
            const float inv = __fdividef(1.f, s);

            float acc0 = 0.f, acc1 = 0.f, acc2 = 0.f, acc3 = 0.f;
            #pragma unroll
            for (int c = 0; c < 7; c++) {
                unsigned w = mw[c];               // warp-uniform
                const float* hb = sm + OFF_H + c * 32 * D1_ + lane;
                const float* ab = al + c * 32;
                while (w) {
                    const int t0 = __ffs(w) - 1; w &= w - 1;
                    acc0 = fmaf(ab[t0], hb[t0 * D1_], acc0);
                    if (!w) break;
                    const int t1 = __ffs(w) - 1; w &= w - 1;
                    acc1 = fmaf(ab[t1], hb[t1 * D1_], acc1);
                    if (!w) break;
                    const int t2 = __ffs(w) - 1; w &= w - 1;
                    acc2 = fmaf(ab[t2], hb[t2 * D1_], acc2);
                    if (!w) break;
                    const int t3 = __ffs(w) - 1; w &= w - 1;
                    acc3 = fmaf(ab[t3], hb[t3 * D1_], acc3);
                }
            }
            sm[OFF_HO + i * D1_ + lane] = ((acc0 + acc1) + (acc2 + acc3)) * inv + b1_l;
        }
    }
    __syncthreads();

    // ============ Phase C: pool-1 scores ====================================
    {
        const float pw1_l = __ldg(&pw1[lane]);
        const float invn1 = __fdividef(1.f, sm[OFF_RED + 0]);
        for (int i = wid; i < N_; i += NW) {
            float s = warpSum(sm[OFF_HO + i * D1_ + lane] * pw1_l);
            if (lane == 0) sm[OFF_SC + i] = __fdividef(1.f, 1.f + __expf(-s * invn1));
        }
    }
    __syncthreads();

    // stable descending rank == jax.lax.top_k order
    if (tid < N_) {
        const float si = sm[OFF_SC + tid];
        int cnt = 0;
        for (int j = 0; j < N_; j++) {
            const float sj = sm[OFF_SC + j];
            cnt += (sj > si) || (sj == si && j < tid);
        }
        if (cnt < K1_) smi[OFF_PERM + cnt] = tid;
    }
    __syncthreads();

    for (int r = tid; r < K1_; r += NT) {
        float v = sm[OFF_SC + smi[OFF_PERM + r]];
        sm[OFF_VAL + r] = v;
        out[512 * 2 + (size_t)b * K1_ + r] = v;
    }
    __syncthreads();

    // gated xk = hout[perm] * vals  (into dead h1 region)
    for (int t = tid; t < K1_ * D1_; t += NT) {
        const int r = t >> 5, d = t & 31;
        sm[OFF_H + t] = sm[OFF_HO + smi[OFF_PERM + r] * D1_ + d] * sm[OFF_VAL + r];
    }
    __syncthreads();

    // x1 readout partials (warps 0-3)
    if (wid < 4) {
        float mx = -INFINITY, s = 0.f;
        for (int r = wid * 25; r < wid * 25 + 25; r++) {
            float v = sm[OFF_H + r * D1_ + lane];
            mx = fmaxf(mx, v);
            s += v;
        }
        sm[OFF_AL + (wid * 2 + 0) * 32 + lane] = mx;
        sm[OFF_AL + (wid * 2 + 1) * 32 + lane] = s;
    }
    // AKB via warp ballot: lane = pooled column
    for (int r = wid; r < K1_; r += NW) {
        const int pr = smi[OFF_PERM + r];
        const unsigned* arow = smu + OFF_ADJB + pr * 7;
        #pragma unroll
        for (int w = 0; w < 4; w++) {
            const int c = w * 32 + lane;
            bool bit = false;
            if (c < K1_) {
                const int pc = smi[OFF_PERM + c];
                bit = (arow[pc >> 5] >> (pc & 31)) & 1u;
            }
            unsigned bal = __ballot_sync(0xffffffffu, bit);
            if (lane == 0) smu[OFF_AKB + r * 4 + w] = bal;
        }
    }
    __syncthreads();   // ADJB dead from here

    // combine x1 partials; a2 = ak | (ak_nz @ ak_nz); stage W2 into ADJB
    if (tid < 32) {
        float mx = fmaxf(fmaxf(sm[OFF_AL + 0 * 32 + lane], sm[OFF_AL + 2 * 32 + lane]),
                         fmaxf(sm[OFF_AL + 4 * 32 + lane], sm[OFF_AL + 6 * 32 + lane]));
        float s = sm[OFF_AL + 1 * 32 + lane] + sm[OFF_AL + 3 * 32 + lane]
                + sm[OFF_AL + 5 * 32 + lane] + sm[OFF_AL + 7 * 32 + lane];
        sm[OFF_Z + lane]      = mx;
        sm[OFF_Z + 32 + lane] = s * (1.f / K1_);
    }
    for (int t = tid; t < K1_ * 4; t += NT) {
        const int r = t >> 2, w = t & 3;
        unsigned acc = smu[OFF_AKB + t];
        #pragma unroll
        for (int kc = 0; kc < 4; kc++) {
            unsigned rw = smu[OFF_AKB + r * 4 + kc];
            while (rw) {
                const int k = __ffs(rw) - 1; rw &= rw - 1;
                acc |= smu[OFF_AKB + (kc * 32 + k) * 4 + w];
            }
        }
        smu[OFF_A2B + t] = acc;
    }
    for (int t = tid; t < D1_ * D2_; t += NT) sm[OFF_ADJB + t] = W2[t];
    __syncthreads();

    // ============ Phase E: GAT2 =============================================
    const float a2s_l = __ldg(&a2s[lane]);
    const float a2d_l = __ldg(&a2d[lane]);
    const float b2_l  = __ldg(&b2[lane]);
    float* sXK   = sm + OFF_H;                 // [100x32]
    float* sH2   = sm + OFF_HO;                // [100x32]
    float* sOUT2 = sm + OFF_HO + K1_ * D2_;    // [100x32]
    float* sW2   = sm + OFF_ADJB;              // [32x32]
    float* sAL2  = sm + OFF_AL;                // [16 x ALP] alpha scratch

    for (int i = wid; i < K1_; i += NW) {
        const float4* xr4 = (const float4*)(sXK + i * D1_);
        float acc = 0.f;
        #pragma unroll
        for (int k4 = 0; k4 < D1_ / 4; k4++) {
            float4 xv = xr4[k4];
            const int k = k4 * 4;
            acc = fmaf(xv.x, sW2[(k + 0) * D2_ + lane], acc);
            acc = fmaf(xv.y, sW2[(k + 1) * D2_ + lane], acc);
            acc = fmaf(xv.z, sW2[(k + 2) * D2_ + lane], acc);
            acc = fmaf(xv.w, sW2[(k + 3) * D2_ + lane], acc);
        }
        sH2[i * D2_ + lane] = acc;
        float es = warpSum(acc * a2s_l);
        float ed = warpSum(acc * a2d_l);
        if (lane == 0) { sm[OFF_ES + i] = es; sm[OFF_ED + i] = ed; }
    }
    __syncthreads();

    // GAT2 attention + aggregation: 2 rows per warp
    for (int g = wid; g < K1_ / 2; g += NW) {
        const int i0 = 2 * g, i1 = i0 + 1;
        const float ed0 = sm[OFF_ED + i0];
        const float ed1 = sm[OFF_ED + i1];
        float* al2 = sAL2 + wid * ALP;
        float alr0[4], alr1[4];
        float mx0 = -INFINITY, mx1 = -INFINITY;
        #pragma unroll
        for (int c = 0; c < 4; c++) {
            const int j = c * 32 + lane;
            float lg0 = NEGF, lg1 = NEGF;
            if (j < K1_) {
                const float esj = sm[OFF_ES + j];
                const unsigned b0 = smu[OFF_A2B + i0 * 4 + c];
                const unsigned b1w = smu[OFF_A2B + i1 * 4 + c];
                if ((j == i0) || ((b0 >> lane) & 1u))  lg0 = lrelu02(ed0 + esj);
                if ((j == i1) || ((b1w >> lane) & 1u)) lg1 = lrelu02(ed1 + esj);
            }
            alr0[c] = lg0; alr1[c] = lg1;
            mx0 = fmaxf(mx0, lg0); mx1 = fmaxf(mx1, lg1);
        }
        mx0 = warpMax(mx0); mx1 = warpMax(mx1);
        float s0 = 0.f, s1 = 0.f;
        #pragma unroll
        for (int c = 0; c < 4; c++) {
            const int j = c * 32 + lane;
            if (j < K1_) {
                float e0 = __expf(alr0[c] - mx0);
                float e1 = __expf(alr1[c] - mx1);
                al2[j] = e0;
                al2[100 + j] = e1;
                s0 += e0; s1 += e1;
            }
        }
        s0 = warpSum(s0); s1 = warpSum(s1);
        const float inv0 = __fdividef(1.f, s0);
        const float inv1 = __fdividef(1.f, s1);

        const float4* a40 = (const float4*)al2;
        const float4* a41 = (const float4*)(al2 + 100);
        float p00 = 0.f, p01 = 0.f, p02 = 0.f, p03 = 0.f;
        float p10 = 0.f, p11 = 0.f, p12 = 0.f, p13 = 0.f;
        #pragma unroll 5
        for (int j4 = 0; j4 < K1_ / 4; j4++) {
            float4 a0 = a40[j4];
            float4 a1 = a41[j4];
            const int j = j4 * 4;
            float h0 = sH2[(j + 0) * D2_ + lane];
            float h1 = sH2[(j + 1) * D2_ + lane];
            float h2 = sH2[(j + 2) * D2_ + lane];
            float h3 = sH2[(j + 3) * D2_ + lane];
            p00 = fmaf(a0.x, h0, p00); p01 = fmaf(a0.y, h1, p01);
            p02 = fmaf(a0.z, h2, p02); p03 = fmaf(a0.w, h3, p03);
            p10 = fmaf(a1.x, h0, p10); p11 = fmaf(a1.y, h1, p11);
            p12 = fmaf(a1.z, h2, p12); p13 = fmaf(a1.w, h3, p13);
        }
        sOUT2[i0 * D2_ + lane] = ((p00 + p01) + (p02 + p03)) * inv0 + b2_l;
        sOUT2[i1 * D2_ + lane] = ((p10 + p11) + (p12 + p13)) * inv1 + b2_l;
    }
    __syncthreads();

    // ============ Phase F: pool-2 ===========================================
    {
        const float pw2_l = __ldg(&pw2[lane]);
        const float invn2 = __fdividef(1.f, sm[OFF_RED + 1]);
        for (int i = wid; i < K1_; i += NW) {
            float s = warpSum(sOUT2[i * D2_ + lane] * pw2_l);
            if (lane == 0) sm[OFF_SC + i] = __fdividef(1.f, 1.f + __expf(-s * invn2));
        }
    }
    __syncthreads();

    if (tid < K1_) {
        const float si = sm[OFF_SC + tid];
        int cnt = 0;
        for (int j = 0; j < K1_; j++) {
            const float sj = sm[OFF_SC + j];
            cnt += (sj > si) || (sj == si && j < tid);
        }
        if (cnt < K2_) smi[OFF_PERM2 + cnt] = tid;
    }
    __syncthreads();

    for (int r = tid; r < K2_; r += NT) {
        float v = sm[OFF_SC + smi[OFF_PERM2 + r]];
        sm[OFF_VAL + r] = v;
        out[512 * 2 + 512 * K1_ + (size_t)b * K2_ + r] = v;
    }
    __syncthreads();

    float* sXK2 = sm + OFF_H + K1_ * D1_;   // [50x32]
    for (int t = tid; t < K2_ * D2_; t += NT) {
        const int r = t >> 5, d = t & 31;
        sXK2[t] = sOUT2[smi[OFF_PERM2 + r] * D2_ + d] * sm[OFF_VAL + r];
    }
    __syncthreads();

    // x2 readout partials (warps 0-1)
    if (wid < 2) {
        float mx = -INFINITY, s = 0.f;
        for (int r = wid * 25; r < wid * 25 + 25; r++) {
            float v = sXK2[r * D2_ + lane];
            mx = fmaxf(mx, v);
            s += v;
        }
        sm[OFF_AL + (wid * 2 + 0) * 32 + lane] = mx;
        sm[OFF_AL + (wid * 2 + 1) * 32 + lane] = s;
    }
    __syncthreads();
    if (tid < 32) {
        float mx = fmaxf(sm[OFF_AL + 0 * 32 + lane], sm[OFF_AL + 2 * 32 + lane]);
        float s  = sm[OFF_AL + 1 * 32 + lane] + sm[OFF_AL + 3 * 32 + lane];
        sm[OFF_Z + 64 + lane] = mx;
        sm[OFF_Z + 96 + lane] = s * (1.f / K2_);
    }
    __syncthreads();

    // ============ Phase G: MLP head (warp 0) ================================
    if (wid == 0) {
        const float invbn = 1.0f / sqrtf(1.0f + 1e-5f);
        float acc = __ldg(&fc1_b[lane]);
        #pragma unroll 4
        for (int k = 0; k < 128; k++) acc = fmaf(sm[OFF_Z + k], __ldg(&fc1_w[k * 32 + lane]), acc);
        acc = fmaxf(acc, 0.f);
        sm[OFF_Z + 128 + lane] = __ldg(&bn4_g[lane]) * acc * invbn + __ldg(&bn4_b[lane]);
        __syncwarp();
        if (lane < 8) {
            float a = __ldg(&fc2_b[lane]);
            #pragma unroll
            for (int k = 0; k < 32; k++) a = fmaf(sm[OFF_Z + 128 + k], __ldg(&fc2_w[k * 8 + lane]), a);
            a = fmaxf(a, 0.f);
            sm[OFF_Z + 160 + lane] = __ldg(&bn5_g[lane]) * a * invbn + __ldg(&bn5_b[lane]);
        }
        __syncwarp();
        if (lane < 2) {
            float a = __ldg(&fc3_b[lane]);
            #pragma unroll
            for (int k = 0; k < 8; k++) a = fmaf(sm[OFF_Z + 160 + k], __ldg(&fc3_w[k * 2 + lane]), a);
            sm[OFF_Z + 170 + lane] = a;
        }
        __syncwarp();
        if (lane == 0) {
            float l0 = sm[OFF_Z + 170], l1 = sm[OFF_Z + 171];
            float m = fmaxf(l0, l1);
            float lse = m + __logf(__expf(l0 - m) + __expf(l1 - m));
            out[(size_t)b * 2 + 0] = l0 - lse;
            out[(size_t)b * 2 + 1] = l1 - lse;
        }
    }
}

extern "C" void kernel_launch(void* const* d_in, const int* in_sizes, int n_in,
                              void* d_out, int out_size) {
    const float* x     = (const float*)d_in[0];
    const float* adj   = (const float*)d_in[1];
    const float* W1    = (const float*)d_in[2];
    const float* a1s   = (const float*)d_in[3];
    const float* a1d   = (const float*)d_in[4];
    const float* b1    = (const float*)d_in[5];
    const float* W2    = (const float*)d_in[6];
    const float* a2s   = (const float*)d_in[7];
    const float* a2d   = (const float*)d_in[8];
    const float* b2    = (const float*)d_in[9];
    const float* pw1   = (const float*)d_in[10];
    const float* pw2   = (const float*)d_in[11];
    const float* fc1w  = (const float*)d_in[12];
    const float* fc1b  = (const float*)d_in[13];
    const float* fc2w  = (const float*)d_in[14];
    const float* fc2b  = (const float*)d_in[15];
    const float* fc3w  = (const float*)d_in[16];
    const float* fc3b  = (const float*)d_in[17];
    const float* bn4g  = (const float*)d_in[18];
    const float* bn4b  = (const float*)d_in[19];
    const float* bn5g  = (const float*)d_in[20];
    const float* bn5b  = (const float*)d_in[21];
    float* out = (float*)d_out;

    k_h<<<dim3(B_, 5), 256>>>(x, W1, a1s, a1d);
    k_adj<<<B_, 256>>>(adj);

    const int smem_bytes = SMEM_FLOATS * (int)sizeof(float);
    cudaFuncSetAttribute(nngat_main, cudaFuncAttributeMaxDynamicSharedMemorySize,
                         smem_bytes);
    nngat_main<<<B_, NT, smem_bytes>>>(
        W2, a2s, a2d, b1, b2, pw1, pw2,
        fc1w, fc1b, fc2w, fc2b, fc3w, fc3b, bn4g, bn4b, bn5g, bn5b, out);
}

// round 10
// speedup vs baseline: 1.1794x; 1.1029x over previous
#include <cuda_runtime.h>
#include <math.h>

// ---------------------------------------------------------------------------
// NNGAT_Net, 2-kernel pipeline:
//  k_pre : blocks 0..511   -> adjacency>0 bitsets (g_adjb)
//          blocks 512..2559-> h = x@W1 (+es/ed) with COALESCED x staging in
//          smem + uniform LDS broadcast (kills the 4-wf uniform-LDG penalty)
//  main  : per-batch GAT1-softmax/agg -> topk -> GAT2 -> topk -> MLP
//          (round-7/9 body: 512 thr, 78.6KB smem, 2 CTAs/SM)
// Output: logp [512*2] | s1 [512*100] | s2 [512*50]
// ---------------------------------------------------------------------------

namespace {
constexpr int B_    = 512;
constexpr int N_    = 200;
constexpr int IND   = 200;
constexpr int D1_   = 32;
constexpr int D2_   = 32;
constexpr int K1_   = 100;
constexpr int K2_   = 50;
constexpr int NT    = 512;          // main kernel: 16 warps
constexpr int NW    = 16;
constexpr int ALP   = 224;          // padded alpha row (7*32)
constexpr float NEGF = -1e9f;

// k_pre: dynamic smem = W1 [200x32] + x tile [50x200]
constexpr int PRE_T   = 320;        // 10 warps
constexpr int PRE_SMEM_FLOATS = 6400 + 10000;   // 65600 bytes

// main-kernel shared memory layout (float indices)
constexpr int OFF_H     = 0;        // 6400: h1 [200x32]; later xk[100x32], xk2[50x32]@+3200
constexpr int OFF_HO    = 6400;     // 6400: hout1 [200x32] -> sH2/sOUT2
constexpr int OFF_AL    = 12800;    // 3584: per-warp alpha rows [16x224]; readout scratch
constexpr int OFF_ES    = 16384;    // 200
constexpr int OFF_ED    = 16584;    // 200
constexpr int OFF_SC    = 16784;    // 200
constexpr int OFF_VAL   = 16984;    // 100
constexpr int OFF_PERM  = 17084;    // 100 (int)
constexpr int OFF_PERM2 = 17184;    // 52  (int)
constexpr int OFF_ADJB  = 17236;    // 1400 (u32): adj bitset [200][7]; later W2 [32x32]
constexpr int OFF_AKB   = 18636;    // 400 (u32)
constexpr int OFF_A2B   = 19036;    // 400 (u32)
constexpr int OFF_Z     = 19436;    // 192
constexpr int OFF_RED   = 19628;    // 32
constexpr int SMEM_FLOATS = 19660;  // 78640 bytes -> 2 CTAs/SM
}

// inter-kernel staging buffers (static device globals: allowed scratch)
__device__ float    g_h[(size_t)B_ * N_ * D1_];   // 13.1 MB
__device__ float    g_es[(size_t)B_ * N_];
__device__ float    g_ed[(size_t)B_ * N_];
__device__ unsigned g_adjb[(size_t)B_ * N_ * 7];  // 2.87 MB

__device__ __forceinline__ float warpMax(float v) {
    #pragma unroll
    for (int o = 16; o > 0; o >>= 1) v = fmaxf(v, __shfl_xor_sync(0xffffffffu, v, o));
    return v;
}
__device__ __forceinline__ float warpSum(float v) {
    #pragma unroll
    for (int o = 16; o > 0; o >>= 1) v += __shfl_xor_sync(0xffffffffu, v, o);
    return v;
}
__device__ __forceinline__ float lrelu02(float x) { return x > 0.f ? x : 0.2f * x; }

// ============ k_pre =========================================================
__global__ __launch_bounds__(PRE_T)
void k_pre(const float* __restrict__ x, const float* __restrict__ adj,
           const float* __restrict__ W1,
           const float* __restrict__ a1s, const float* __restrict__ a1d)
{
    extern __shared__ float sp[];
    const int tid  = threadIdx.x;
    const int lane = tid & 31;
    const int wid  = tid >> 5;

    if (blockIdx.x < B_) {
        // ---- adjacency > 0 -> bitsets ----
        const int b = blockIdx.x;
        const float* adjb = adj + (size_t)b * N_ * N_;
        for (int i = wid; i < N_; i += 10) {
            #pragma unroll
            for (int c = 0; c < 7; c++) {
                const int j = c * 32 + lane;
                float w = (j < N_) ? adjb[i * N_ + j] : 0.f;
                unsigned bal = __ballot_sync(0xffffffffu, w > 0.f);
                if (lane == 0) g_adjb[((size_t)b * N_ + i) * 7 + c] = bal;
            }
        }
        return;
    }

    // ---- h = x @ W1 ; es/ed for one 50-row tile ----
    const int blk = blockIdx.x - B_;
    const int b = blk >> 2;
    const int y = blk & 3;
    float* sW = sp;            // [200 x 32]
    float* sX = sp + 6400;     // [50 x 200]

    {
        const float4* w4 = (const float4*)W1;
        float4* d4 = (float4*)sW;
        for (int t = tid; t < IND * D1_ / 4; t += PRE_T) d4[t] = w4[t];
        const float4* x4 = (const float4*)(x + (size_t)b * N_ * IND + (size_t)y * 50 * IND);
        float4* sx4 = (float4*)sX;
        for (int t = tid; t < 50 * IND / 4; t += PRE_T) sx4[t] = x4[t];
    }
    __syncthreads();

    const float a1s_l = __ldg(&a1s[lane]);
    const float a1d_l = __ldg(&a1d[lane]);
    const int lr = wid * 5;          // local row base (0..45)
    const int ib = y * 50 + lr;      // global row base

    const float4* xr0 = (const float4*)(sX + (lr + 0) * IND);
    const float4* xr1 = (const float4*)(sX + (lr + 1) * IND);
    const float4* xr2 = (const float4*)(sX + (lr + 2) * IND);
    const float4* xr3 = (const float4*)(sX + (lr + 3) * IND);
    const float4* xr4p = (const float4*)(sX + (lr + 4) * IND);
    float a0 = 0.f, a1 = 0.f, a2 = 0.f, a3 = 0.f, a4 = 0.f;
    #pragma unroll 2
    for (int k4 = 0; k4 < IND / 4; k4++) {
        float4 v0 = xr0[k4];     // uniform LDS.128 broadcast: 1 wavefront
        float4 v1 = xr1[k4];
        float4 v2 = xr2[k4];
        float4 v3 = xr3[k4];
        float4 v4 = xr4p[k4];
        const int k = k4 * 4;
        float w0 = sW[(k + 0) * D1_ + lane];
        float w1 = sW[(k + 1) * D1_ + lane];
        float w2 = sW[(k + 2) * D1_ + lane];
        float w3 = sW[(k + 3) * D1_ + lane];
        a0 = fmaf(v0.x, w0, fmaf(v0.y, w1, fmaf(v0.z, w2, fmaf(v0.w, w3, a0))));
        a1 = fmaf(v1.x, w0, fmaf(v1.y, w1, fmaf(v1.z, w2, fmaf(v1.w, w3, a1))));
        a2 = fmaf(v2.x, w0, fmaf(v2.y, w1, fmaf(v2.z, w2, fmaf(v2.w, w3, a2))));
        a3 = fmaf(v3.x, w0, fmaf(v3.y, w1, fmaf(v3.z, w2, fmaf(v3.w, w3, a3))));
        a4 = fmaf(v4.x, w0, fmaf(v4.y, w1, fmaf(v4.z, w2, fmaf(v4.w, w3, a4))));
    }
    float hr[5] = {a0, a1, a2, a3, a4};
    #pragma unroll
    for (int r = 0; r < 5; r++) {
        const size_t row = (size_t)b * N_ + (ib + r);
        g_h[row * D1_ + lane] = hr[r];
        float es = warpSum(hr[r] * a1s_l);
        float ed = warpSum(hr[r] * a1d_l);
        if (lane == 0) { g_es[row] = es; g_ed[row] = ed; }
    }
}

// ============ main kernel ===================================================
__global__ __launch_bounds__(NT, 2)
void nngat_main(
    const float* __restrict__ W2,    const float* __restrict__ a2s,
    const float* __restrict__ a2d,   const float* __restrict__ b1,
    const float* __restrict__ b2,
    const float* __restrict__ pw1,   const float* __restrict__ pw2,
    const float* __restrict__ fc1_w, const float* __restrict__ fc1_b,
    const float* __restrict__ fc2_w, const float* __restrict__ fc2_b,
    const float* __restrict__ fc3_w, const float* __restrict__ fc3_b,
    const float* __restrict__ bn4_g, const float* __restrict__ bn4_b,
    const float* __restrict__ bn5_g, const float* __restrict__ bn5_b,
    float* __restrict__ out)
{
    extern __shared__ float sm[];
    int*      smi = (int*)sm;
    unsigned* smu = (unsigned*)sm;

    const int b    = blockIdx.x;
    const int tid  = threadIdx.x;
    const int lane = tid & 31;
    const int wid  = tid >> 5;

    // ---- stage h, es/ed, adj bitsets from the pre-kernel; pw norms ----
    {
        const float4* h4 = (const float4*)(g_h + (size_t)b * N_ * D1_);
        float4* d4 = (float4*)(sm + OFF_H);
        for (int t = tid; t < N_ * D1_ / 4; t += NT) d4[t] = h4[t];
    }
    for (int t = tid; t < N_; t += NT) {
        sm[OFF_ES + t] = g_es[(size_t)b * N_ + t];
        sm[OFF_ED + t] = g_ed[(size_t)b * N_ + t];
    }
    for (int t = tid; t < N_ * 7; t += NT)
        smu[OFF_ADJB + t] = g_adjb[(size_t)b * N_ * 7 + t];
    if (wid == 0) {
        float v = pw1[lane];
        float s = warpSum(v * v);
        if (lane == 0) sm[OFF_RED + 0] = sqrtf(s) + 1e-16f;
    }
    if (wid == 1) {
        float v = pw2[lane];
        float s = warpSum(v * v);
        if (lane == 0) sm[OFF_RED + 1] = sqrtf(s) + 1e-16f;
    }
    __syncthreads();

    const float b1_l = __ldg(&b1[lane]);

    // ============ Phase B: GAT1 softmax + sparse agg (bitsets in smem) ======
    {
        float* al = sm + OFF_AL + wid * ALP;
        for (int i = wid; i < N_; i += NW) {
            const float edi = sm[OFF_ED + i];
            unsigned mw[7];
            float alr[7];
            float mx = -INFINITY;
            #pragma unroll
            for (int c = 0; c < 7; c++) {
                unsigned bal = smu[OFF_ADJB + i * 7 + c];
                if ((i >> 5) == c) bal |= 1u << (i & 31);   // self-loop
                mw[c] = bal;
                float lg = NEGF;
                const int j = c * 32 + lane;
                if ((bal >> lane) & 1u) lg = lrelu02(edi + sm[OFF_ES + j]);
                alr[c] = lg;
                mx = fmaxf(mx, lg);
            }
            mx = warpMax(mx);

            float s = 0.f;
            #pragma unroll
            for (int c = 0; c < 7; c++) {
                float e = __expf(alr[c] - mx);    // masked lanes underflow to 0
                al[c * 32 + lane] = e;            // padded row: in-bounds
                s += e;
            }
            s = warpSum(s);
            const float inv = __fdividef(1.f, s);

            float acc0 = 0.f, acc1 = 0.f, acc2 = 0.f, acc3 = 0.f;
            #pragma unroll
            for (int c = 0; c < 7; c++) {
                unsigned w = mw[c];               // warp-uniform
                const float* hb = sm + OFF_H + c * 32 * D1_ + lane;
                const float* ab = al + c * 32;
                while (w) {
                    const int t0 = __ffs(w) - 1; w &= w - 1;
                    acc0 = fmaf(ab[t0], hb[t0 * D1_], acc0);
                    if (!w) break;
                    const int t1 = __ffs(w) - 1; w &= w - 1;
                    acc1 = fmaf(ab[t1], hb[t1 * D1_], acc1);
                    if (!w) break;
                    const int t2 = __ffs(w) - 1; w &= w - 1;
                    acc2 = fmaf(ab[t2], hb[t2 * D1_], acc2);
                    if (!w) break;
                    const int t3 = __ffs(w) - 1; w &= w - 1;
                    acc3 = fmaf(ab[t3], hb[t3 * D1_], acc3);
                }
            }
            sm[OFF_HO + i * D1_ + lane] = ((acc0 + acc1) + (acc2 + acc3)) * inv + b1_l;
        }
    }
    __syncthreads();

    // ============ Phase C: pool-1 scores ====================================
    {
        const float pw1_l = __ldg(&pw1[lane]);
        const float invn1 = __fdividef(1.f, sm[OFF_RED + 0]);
        for (int i = wid; i < N_; i += NW) {
            float s = warpSum(sm[OFF_HO + i * D1_ + lane] * pw1_l);
            if (lane == 0) sm[OFF_SC + i] = __fdividef(1.f, 1.f + __expf(-s * invn1));
        }
    }
    __syncthreads();

    // stable descending rank == jax.lax.top_k order
    if (tid < N_) {
        const float si = sm[OFF_SC + tid];
        int cnt = 0;
        for (int j = 0; j < N_; j++) {
            const float sj = sm[OFF_SC + j];
            cnt += (sj > si) || (sj == si && j < tid);
        }
        if (cnt < K1_) smi[OFF_PERM + cnt] = tid;
    }
    __syncthreads();

    for (int r = tid; r < K1_; r += NT) {
        float v = sm[OFF_SC + smi[OFF_PERM + r]];
        sm[OFF_VAL + r] = v;
        out[512 * 2 + (size_t)b * K1_ + r] = v;
    }
    __syncthreads();

    // gated xk = hout[perm] * vals  (into dead h1 region)
    for (int t = tid; t < K1_ * D1_; t += NT) {
        const int r = t >> 5, d = t & 31;
        sm[OFF_H + t] = sm[OFF_HO + smi[OFF_PERM + r] * D1_ + d] * sm[OFF_VAL + r];
    }
    __syncthreads();

    // x1 readout partials (warps 0-3)
    if (wid < 4) {
        float mx = -INFINITY, s = 0.f;
        for (int r = wid * 25; r < wid * 25 + 25; r++) {
            float v = sm[OFF_H + r * D1_ + lane];
            mx = fmaxf(mx, v);
            s += v;
        }
        sm[OFF_AL + (wid * 2 + 0) * 32 + lane] = mx;
        sm[OFF_AL + (wid * 2 + 1) * 32 + lane] = s;
    }
    // AKB via warp ballot: lane = pooled column
    for (int r = wid; r < K1_; r += NW) {
        const int pr = smi[OFF_PERM + r];
        const unsigned* arow = smu + OFF_ADJB + pr * 7;
        #pragma unroll
        for (int w = 0; w < 4; w++) {
            const int c = w * 32 + lane;
            bool bit = false;
            if (c < K1_) {
                const int pc = smi[OFF_PERM + c];
                bit = (arow[pc >> 5] >> (pc & 31)) & 1u;
            }
            unsigned bal = __ballot_sync(0xffffffffu, bit);
            if (lane == 0) smu[OFF_AKB + r * 4 + w] = bal;
        }
    }
    __syncthreads();   // ADJB dead from here

    // combine x1 partials; a2 = ak | (ak_nz @ ak_nz); stage W2 into ADJB
    if (tid < 32) {
        float mx = fmaxf(fmaxf(sm[OFF_AL + 0 * 32 + lane], sm[OFF_AL + 2 * 32 + lane]),
                         fmaxf(sm[OFF_AL + 4 * 32 + lane], sm[OFF_AL + 6 * 32 + lane]));
        float s = sm[OFF_AL + 1 * 32 + lane] + sm[OFF_AL + 3 * 32 + lane]
                + sm[OFF_AL + 5 * 32 + lane] + sm[OFF_AL + 7 * 32 + lane];
        sm[OFF_Z + lane]      = mx;
        sm[OFF_Z + 32 + lane] = s * (1.f / K1_);
    }
    for (int t = tid; t < K1_ * 4; t += NT) {
        const int r = t >> 2, w = t & 3;
        unsigned acc = smu[OFF_AKB + t];
        #pragma unroll
        for (int kc = 0; kc < 4; kc++) {
            unsigned rw = smu[OFF_AKB + r * 4 + kc];
            while (rw) {
                const int k = __ffs(rw) - 1; rw &= rw - 1;
                acc |= smu[OFF_AKB + (kc * 32 + k) * 4 + w];
            }
        }
        smu[OFF_A2B + t] = acc;
    }
    for (int t = tid; t < D1_ * D2_; t += NT) sm[OFF_ADJB + t] = W2[t];
    __syncthreads();

    // ============ Phase E: GAT2 =============================================
    const float a2s_l = __ldg(&a2s[lane]);
    const float a2d_l = __ldg(&a2d[lane]);
    const float b2_l  = __ldg(&b2[lane]);
    float* sXK   = sm + OFF_H;                 // [100x32]
    float* sH2   = sm + OFF_HO;                // [100x32]
    float* sOUT2 = sm + OFF_HO + K1_ * D2_;    // [100x32]
    float* sW2   = sm + OFF_ADJB;              // [32x32]
    float* sAL2  = sm + OFF_AL;                // [16 x ALP] alpha scratch

    for (int i = wid; i < K1_; i += NW) {
        const float4* xr4 = (const float4*)(sXK + i * D1_);
        float acc = 0.f;
        #pragma unroll
        for (int k4 = 0; k4 < D1_ / 4; k4++) {
            float4 xv = xr4[k4];
            const int k = k4 * 4;
            acc = fmaf(xv.x, sW2[(k + 0) * D2_ + lane], acc);
            acc = fmaf(xv.y, sW2[(k + 1) * D2_ + lane], acc);
            acc = fmaf(xv.z, sW2[(k + 2) * D2_ + lane], acc);
            acc = fmaf(xv.w, sW2[(k + 3) * D2_ + lane], acc);
        }
        sH2[i * D2_ + lane] = acc;
        float es = warpSum(acc * a2s_l);
        float ed = warpSum(acc * a2d_l);
        if (lane == 0) { sm[OFF_ES + i] = es; sm[OFF_ED + i] = ed; }
    }
    __syncthreads();

    // GAT2 attention + aggregation: 2 rows per warp
    for (int g = wid; g < K1_ / 2; g += NW) {
        const int i0 = 2 * g, i1 = i0 + 1;
        const float ed0 = sm[OFF_ED + i0];
        const float ed1 = sm[OFF_ED + i1];
        float* al2 = sAL2 + wid * ALP;
        float alr0[4], alr1[4];
        float mx0 = -INFINITY, mx1 = -INFINITY;
        #pragma unroll
        for (int c = 0; c < 4; c++) {
            const int j = c * 32 + lane;
            float lg0 = NEGF, lg1 = NEGF;
            if (j < K1_) {
                const float esj = sm[OFF_ES + j];
                const unsigned b0 = smu[OFF_A2B + i0 * 4 + c];
                const unsigned b1w = smu[OFF_A2B + i1 * 4 + c];
                if ((j == i0) || ((b0 >> lane) & 1u))  lg0 = lrelu02(ed0 + esj);
                if ((j == i1) || ((b1w >> lane) & 1u)) lg1 = lrelu02(ed1 + esj);
            }
            alr0[c] = lg0; alr1[c] = lg1;
            mx0 = fmaxf(mx0, lg0); mx1 = fmaxf(mx1, lg1);
        }
        mx0 = warpMax(mx0); mx1 = warpMax(mx1);
        float s0 = 0.f, s1 = 0.f;
        #pragma unroll
        for (int c = 0; c < 4; c++) {
            const int j = c * 32 + lane;
            if (j < K1_) {
                float e0 = __expf(alr0[c] - mx0);
                float e1 = __expf(alr1[c] - mx1);
                al2[j] = e0;
                al2[100 + j] = e1;
                s0 += e0; s1 += e1;
            }
        }
        s0 = warpSum(s0); s1 = warpSum(s1);
        const float inv0 = __fdividef(1.f, s0);
        const float inv1 = __fdividef(1.f, s1);

        const float4* a40 = (const float4*)al2;
        const float4* a41 = (const float4*)(al2 + 100);
        float p00 = 0.f, p01 = 0.f, p02 = 0.f, p03 = 0.f;
        float p10 = 0.f, p11 = 0.f, p12 = 0.f, p13 = 0.f;
        #pragma unroll 5
        for (int j4 = 0; j4 < K1_ / 4; j4++) {
            float4 a0 = a40[j4];
            float4 a1 = a41[j4];
            const int j = j4 * 4;
            float h0 = sH2[(j + 0) * D2_ + lane];
            float h1 = sH2[(j + 1) * D2_ + lane];
            float h2 = sH2[(j + 2) * D2_ + lane];
            float h3 = sH2[(j + 3) * D2_ + lane];
            p00 = fmaf(a0.x, h0, p00); p01 = fmaf(a0.y, h1, p01);
            p02 = fmaf(a0.z, h2, p02); p03 = fmaf(a0.w, h3, p03);
            p10 = fmaf(a1.x, h0, p10); p11 = fmaf(a1.y, h1, p11);
            p12 = fmaf(a1.z, h2, p12); p13 = fmaf(a1.w, h3, p13);
        }
        sOUT2[i0 * D2_ + lane] = ((p00 + p01) + (p02 + p03)) * inv0 + b2_l;
        sOUT2[i1 * D2_ + lane] = ((p10 + p11) + (p12 + p13)) * inv1 + b2_l;
    }
    __syncthreads();

    // ============ Phase F: pool-2 ===========================================
    {
        const float pw2_l = __ldg(&pw2[lane]);
        const float invn2 = __fdividef(1.f, sm[OFF_RED + 1]);
        for (int i = wid; i < K1_; i += NW) {
            float s = warpSum(sOUT2[i * D2_ + lane] * pw2_l);
            if (lane == 0) sm[OFF_SC + i] = __fdividef(1.f, 1.f + __expf(-s * invn2));
        }
    }
    __syncthreads();

    if (tid < K1_) {
        const float si = sm[OFF_SC + tid];
        int cnt = 0;
        for (int j = 0; j < K1_; j++) {
            const float sj = sm[OFF_SC + j];
            cnt += (sj > si) || (sj == si && j < tid);
        }
        if (cnt < K2_) smi[OFF_PERM2 + cnt] = tid;
    }
    __syncthreads();

    for (int r = tid; r < K2_; r += NT) {
        float v = sm[OFF_SC + smi[OFF_PERM2 + r]];
        sm[OFF_VAL + r] = v;
        out[512 * 2 + 512 * K1_ + (size_t)b * K2_ + r] = v;
    }
    __syncthreads();

    float* sXK2 = sm + OFF_H + K1_ * D1_;   // [50x32]
    for (int t = tid; t < K2_ * D2_; t += NT) {
        const int r = t >> 5, d = t & 31;
        sXK2[t] = sOUT2[smi[OFF_PERM2 + r] * D2_ + d] * sm[OFF_VAL + r];
    }
    __syncthreads();

    // x2 readout partials (warps 0-1)
    if (wid < 2) {
        float mx = -INFINITY, s = 0.f;
        for (int r = wid * 25; r < wid * 25 + 25; r++) {
            float v = sXK2[r * D2_ + lane];
            mx = fmaxf(mx, v);
            s += v;
        }
        sm[OFF_AL + (wid * 2 + 0) * 32 + lane] = mx;
        sm[OFF_AL + (wid * 2 + 1) * 32 + lane] = s;
    }
    __syncthreads();
    if (tid < 32) {
        float mx = fmaxf(sm[OFF_AL + 0 * 32 + lane], sm[OFF_AL + 2 * 32 + lane]);
        float s  = sm[OFF_AL + 1 * 32 + lane] + sm[OFF_AL + 3 * 32 + lane];
        sm[OFF_Z + 64 + lane] = mx;
        sm[OFF_Z + 96 + lane] = s * (1.f / K2_);
    }
    __syncthreads();

    // ============ Phase G: MLP head (warp 0) ================================
    if (wid == 0) {
        const float invbn = 1.0f / sqrtf(1.0f + 1e-5f);
        float acc = __ldg(&fc1_b[lane]);
        #pragma unroll 4
        for (int k = 0; k < 128; k++) acc = fmaf(sm[OFF_Z + k], __ldg(&fc1_w[k * 32 + lane]), acc);
        acc = fmaxf(acc, 0.f);
        sm[OFF_Z + 128 + lane] = __ldg(&bn4_g[lane]) * acc * invbn + __ldg(&bn4_b[lane]);
        __syncwarp();
        if (lane < 8) {
            float a = __ldg(&fc2_b[lane]);
            #pragma unroll
            for (int k = 0; k < 32; k++) a = fmaf(sm[OFF_Z + 128 + k], __ldg(&fc2_w[k * 8 + lane]), a);
            a = fmaxf(a, 0.f);
            sm[OFF_Z + 160 + lane] = __ldg(&bn5_g[lane]) * a * invbn + __ldg(&bn5_b[lane]);
        }
        __syncwarp();
        if (lane < 2) {
            float a = __ldg(&fc3_b[lane]);
            #pragma unroll
            for (int k = 0; k < 8; k++) a = fmaf(sm[OFF_Z + 160 + k], __ldg(&fc3_w[k * 2 + lane]), a);
            sm[OFF_Z + 170 + lane] = a;
        }
        __syncwarp();
        if (lane == 0) {
            float l0 = sm[OFF_Z + 170], l1 = sm[OFF_Z + 171];
            float m = fmaxf(l0, l1);
            float lse = m + __logf(__expf(l0 - m) + __expf(l1 - m));
            out[(size_t)b * 2 + 0] = l0 - lse;
            out[(size_t)b * 2 + 1] = l1 - lse;
        }
    }
}

extern "C" void kernel_launch(void* const* d_in, const int* in_sizes, int n_in,
                              void* d_out, int out_size) {
    const float* x     = (const float*)d_in[0];
    const float* adj   = (const float*)d_in[1];
    const float* W1    = (const float*)d_in[2];
    const float* a1s   = (const float*)d_in[3];
    const float* a1d   = (const float*)d_in[4];
    const float* b1    = (const float*)d_in[5];
    const float* W2    = (const float*)d_in[6];
    const float* a2s   = (const float*)d_in[7];
    const float* a2d   = (const float*)d_in[8];
    const float* b2    = (const float*)d_in[9];
    const float* pw1   = (const float*)d_in[10];
    const float* pw2   = (const float*)d_in[11];
    const float* fc1w  = (const float*)d_in[12];
    const float* fc1b  = (const float*)d_in[13];
    const float* fc2w  = (const float*)d_in[14];
    const float* fc2b  = (const float*)d_in[15];
    const float* fc3w  = (const float*)d_in[16];
    const float* fc3b  = (const float*)d_in[17];
    const float* bn4g  = (const float*)d_in[18];
    const float* bn4b  = (const float*)d_in[19];
    const float* bn5g  = (const float*)d_in[20];
    const float* bn5b  = (const float*)d_in[21];
    float* out = (float*)d_out;

    const int pre_smem = PRE_SMEM_FLOATS * (int)sizeof(float);
    cudaFuncSetAttribute(k_pre, cudaFuncAttributeMaxDynamicSharedMemorySize, pre_smem);
    k_pre<<<B_ + B_ * 4, PRE_T, pre_smem>>>(x, adj, W1, a1s, a1d);

    const int smem_bytes = SMEM_FLOATS * (int)sizeof(float);
    cudaFuncSetAttribute(nngat_main, cudaFuncAttributeMaxDynamicSharedMemorySize,
                         smem_bytes);
    nngat_main<<<B_, NT, smem_bytes>>>(
        W2, a2s, a2d, b1, b2, pw1, pw2,
        fc1w, fc1b, fc2w, fc2b, fc3w, fc3b, bn4g, bn4b, bn5g, bn5b, out);
}

// round 11
// speedup vs baseline: 1.1828x; 1.0029x over previous
#include <cuda_runtime.h>
#include <math.h>

// ---------------------------------------------------------------------------
// NNGAT_Net, 2-kernel pipeline:
//  k_pre : blocks 0..511    -> adjacency>0 bitsets (g_adjb)
//          blocks 512..3071 -> h = x@W1 (+es/ed), SHUFFLE-BROADCAST GEMM:
//          x loaded coalesced (1 wf / 32 vals), broadcast via shfl -> kills
//          the 4-wf uniform-load wavefront tax (24.6M wf -> ~5.8M wf).
//  main  : per-batch GAT1-softmax/agg -> topk -> GAT2 -> topk -> MLP
// Output: logp [512*2] | s1 [512*100] | s2 [512*50]
// ---------------------------------------------------------------------------

namespace {
constexpr int B_    = 512;
constexpr int N_    = 200;
constexpr int IND   = 200;
constexpr int D1_   = 32;
constexpr int D2_   = 32;
constexpr int K1_   = 100;
constexpr int K2_   = 50;
constexpr int NT    = 512;          // main kernel: 16 warps
constexpr int NW    = 16;
constexpr int ALP   = 224;          // padded alpha row (7*32)
constexpr float NEGF = -1e9f;

// main-kernel shared memory layout (float indices)
constexpr int OFF_H     = 0;        // 6400: h1 [200x32]; later xk[100x32], xk2[50x32]@+3200
constexpr int OFF_HO    = 6400;     // 6400: hout1 [200x32] -> sH2/sOUT2
constexpr int OFF_AL    = 12800;    // 3584: per-warp alpha rows [16x224]; readout scratch
constexpr int OFF_ES    = 16384;    // 200
constexpr int OFF_ED    = 16584;    // 200
constexpr int OFF_SC    = 16784;    // 200
constexpr int OFF_VAL   = 16984;    // 100
constexpr int OFF_PERM  = 17084;    // 100 (int)
constexpr int OFF_PERM2 = 17184;    // 52  (int)
constexpr int OFF_ADJB  = 17236;    // 1400 (u32): adj bitset [200][7]; later W2 [32x32]
constexpr int OFF_AKB   = 18636;    // 400 (u32)
constexpr int OFF_A2B   = 19036;    // 400 (u32)
constexpr int OFF_Z     = 19436;    // 192
constexpr int OFF_RED   = 19628;    // 32
constexpr int SMEM_FLOATS = 19660;  // 78640 bytes -> 2 CTAs/SM
}

// inter-kernel staging buffers (static device globals: allowed scratch)
__device__ float    g_h[(size_t)B_ * N_ * D1_];   // 13.1 MB
__device__ float    g_es[(size_t)B_ * N_];
__device__ float    g_ed[(size_t)B_ * N_];
__device__ unsigned g_adjb[(size_t)B_ * N_ * 7];  // 2.87 MB

__device__ __forceinline__ float warpMax(float v) {
    #pragma unroll
    for (int o = 16; o > 0; o >>= 1) v = fmaxf(v, __shfl_xor_sync(0xffffffffu, v, o));
    return v;
}
__device__ __forceinline__ float warpSum(float v) {
    #pragma unroll
    for (int o = 16; o > 0; o >>= 1) v += __shfl_xor_sync(0xffffffffu, v, o);
    return v;
}
__device__ __forceinline__ float lrelu02(float x) { return x > 0.f ? x : 0.2f * x; }

// ============ k_pre =========================================================
// blocks [0, B): adjacency bitsets. blocks [B, B+5B): h-tiles of 40 rows
// (8 warps x 5 rows), shuffle-broadcast GEMM.
__global__ __launch_bounds__(256)
void k_pre(const float* __restrict__ x, const float* __restrict__ adj,
           const float* __restrict__ W1,
           const float* __restrict__ a1s, const float* __restrict__ a1d)
{
    __shared__ float sW[IND * D1_];   // 25.6 KB
    const int tid  = threadIdx.x;
    const int lane = tid & 31;
    const int wid  = tid >> 5;

    if (blockIdx.x < B_) {
        // ---- adjacency > 0 -> bitsets ----
        const int b = blockIdx.x;
        const float* adjb = adj + (size_t)b * N_ * N_;
        for (int i = wid; i < N_; i += 8) {
            #pragma unroll
            for (int c = 0; c < 7; c++) {
                const int j = c * 32 + lane;
                float w = (j < N_) ? adjb[i * N_ + j] : 0.f;
                unsigned bal = __ballot_sync(0xffffffffu, w > 0.f);
                if (lane == 0) g_adjb[((size_t)b * N_ + i) * 7 + c] = bal;
            }
        }
        return;
    }

    // ---- h-tile: 40 rows; warp handles 5 rows via shuffle-broadcast ----
    {
        const float4* w4 = (const float4*)W1;
        float4* d4 = (float4*)sW;
        for (int t = tid; t < IND * D1_ / 4; t += 256) d4[t] = w4[t];
    }
    __syncthreads();

    const int blk = blockIdx.x - B_;
    const int b = blk / 5;
    const int y = blk % 5;
    const int ib = y * 40 + wid * 5;
    const float* xrp = x + ((size_t)b * N_ + ib) * IND;

    const float a1s_l = __ldg(&a1s[lane]);
    const float a1d_l = __ldg(&a1d[lane]);

    float acc0 = 0.f, acc1 = 0.f, acc2 = 0.f, acc3 = 0.f, acc4 = 0.f;
    // chunk 0 coalesced x loads (lane = k offset)
    float xr0 = __ldg(xrp + 0 * IND + lane);
    float xr1 = __ldg(xrp + 1 * IND + lane);
    float xr2 = __ldg(xrp + 2 * IND + lane);
    float xr3 = __ldg(xrp + 3 * IND + lane);
    float xr4 = __ldg(xrp + 4 * IND + lane);

    #pragma unroll
    for (int c = 0; c < 7; c++) {
        // prefetch next chunk
        float xn0 = 0.f, xn1 = 0.f, xn2 = 0.f, xn3 = 0.f, xn4 = 0.f;
        if (c < 6) {
            const int kn = (c + 1) * 32 + lane;
            if (kn < IND) {
                xn0 = __ldg(xrp + 0 * IND + kn);
                xn1 = __ldg(xrp + 1 * IND + kn);
                xn2 = __ldg(xrp + 2 * IND + kn);
                xn3 = __ldg(xrp + 3 * IND + kn);
                xn4 = __ldg(xrp + 4 * IND + kn);
            }
        }
        const int tmax = (c < 6) ? 32 : 8;   // chunk 6 covers k=192..199
        const float* wbase = sW + c * 32 * D1_ + lane;
        #pragma unroll 8
        for (int t = 0; t < tmax; t++) {
            const float w = wbase[t * D1_];              // lane-indexed: 1 wf
            acc0 = fmaf(__shfl_sync(0xffffffffu, xr0, t), w, acc0);
            acc1 = fmaf(__shfl_sync(0xffffffffu, xr1, t), w, acc1);
            acc2 = fmaf(__shfl_sync(0xffffffffu, xr2, t), w, acc2);
            acc3 = fmaf(__shfl_sync(0xffffffffu, xr3, t), w, acc3);
            acc4 = fmaf(__shfl_sync(0xffffffffu, xr4, t), w, acc4);
        }
        xr0 = xn0; xr1 = xn1; xr2 = xn2; xr3 = xn3; xr4 = xn4;
    }

    float hr[5] = {acc0, acc1, acc2, acc3, acc4};
    #pragma unroll
    for (int r = 0; r < 5; r++) {
        const size_t row = (size_t)b * N_ + (ib + r);
        g_h[row * D1_ + lane] = hr[r];
        float es = warpSum(hr[r] * a1s_l);
        float ed = warpSum(hr[r] * a1d_l);
        if (lane == 0) { g_es[row] = es; g_ed[row] = ed; }
    }
}

// ============ main kernel ===================================================
__global__ __launch_bounds__(NT, 2)
void nngat_main(
    const float* __restrict__ W2,    const float* __restrict__ a2s,
    const float* __restrict__ a2d,   const float* __restrict__ b1,
    const float* __restrict__ b2,
    const float* __restrict__ pw1,   const float* __restrict__ pw2,
    const float* __restrict__ fc1_w, const float* __restrict__ fc1_b,
    const float* __restrict__ fc2_w, const float* __restrict__ fc2_b,
    const float* __restrict__ fc3_w, const float* __restrict__ fc3_b,
    const float* __restrict__ bn4_g, const float* __restrict__ bn4_b,
    const float* __restrict__ bn5_g, const float* __restrict__ bn5_b,
    float* __restrict__ out)
{
    extern __shared__ float sm[];
    int*      smi = (int*)sm;
    unsigned* smu = (unsigned*)sm;

    const int b    = blockIdx.x;
    const int tid  = threadIdx.x;
    const int lane = tid & 31;
    const int wid  = tid >> 5;

    // ---- stage h, es/ed, adj bitsets from the pre-kernel; pw norms ----
    {
        const float4* h4 = (const float4*)(g_h + (size_t)b * N_ * D1_);
        float4* d4 = (float4*)(sm + OFF_H);
        for (int t = tid; t < N_ * D1_ / 4; t += NT) d4[t] = h4[t];
    }
    for (int t = tid; t < N_; t += NT) {
        sm[OFF_ES + t] = g_es[(size_t)b * N_ + t];
        sm[OFF_ED + t] = g_ed[(size_t)b * N_ + t];
    }
    for (int t = tid; t < N_ * 7; t += NT)
        smu[OFF_ADJB + t] = g_adjb[(size_t)b * N_ * 7 + t];
    if (wid == 0) {
        float v = pw1[lane];
        float s = warpSum(v * v);
        if (lane == 0) sm[OFF_RED + 0] = sqrtf(s) + 1e-16f;
    }
    if (wid == 1) {
        float v = pw2[lane];
        float s = warpSum(v * v);
        if (lane == 0) sm[OFF_RED + 1] = sqrtf(s) + 1e-16f;
    }
    __syncthreads();

    const float b1_l = __ldg(&b1[lane]);

    // ============ Phase B: GAT1 softmax + sparse agg (bitsets in smem) ======
    {
        float* al = sm + OFF_AL + wid * ALP;
        for (int i = wid; i < N_; i += NW) {
            const float edi = sm[OFF_ED + i];
            unsigned mw[7];
            float alr[7];
            float mx = -INFINITY;
            #pragma unroll
            for (int c = 0; c < 7; c++) {
                unsigned bal = smu[OFF_ADJB + i * 7 + c];
                if ((i >> 5) == c) bal |= 1u << (i & 31);   // self-loop
                mw[c] = bal;
                float lg = NEGF;
                const int j = c * 32 + lane;
                if ((bal >> lane) & 1u) lg = lrelu02(edi + sm[OFF_ES + j]);
                alr[c] = lg;
                mx = fmaxf(mx, lg);
            }
            mx = warpMax(mx);

            float s = 0.f;
            #pragma unroll
            for (int c = 0; c < 7; c++) {
                float e = __expf(alr[c] - mx);    // masked lanes underflow to 0
                al[c * 32 + lane] = e;            // padded row: in-bounds
                s += e;
            }
            s = warpSum(s);
            const float inv = __fdividef(1.f, s);

            float acc0 = 0.f, acc1 = 0.f, acc2 = 0.f, acc3 = 0.f;
            #pragma unroll
            for (int c = 0; c < 7; c++) {
                unsigned w = mw[c];               // warp-uniform
                const float* hb = sm + OFF_H + c * 32 * D1_ + lane;
                const float* ab = al + c * 32;
                while (w) {
                    const int t0 = __ffs(w) - 1; w &= w - 1;
                    acc0 = fmaf(ab[t0], hb[t0 * D1_], acc0);
                    if (!w) break;
                    const int t1 = __ffs(w) - 1; w &= w - 1;
                    acc1 = fmaf(ab[t1], hb[t1 * D1_], acc1);
                    if (!w) break;
                    const int t2 = __ffs(w) - 1; w &= w - 1;
                    acc2 = fmaf(ab[t2], hb[t2 * D1_], acc2);
                    if (!w) break;
                    const int t3 = __ffs(w) - 1; w &= w - 1;
                    acc3 = fmaf(ab[t3], hb[t3 * D1_], acc3);
                }
            }
            sm[OFF_HO + i * D1_ + lane] = ((acc0 + acc1) + (acc2 + acc3)) * inv + b1_l;
        }
    }
    __syncthreads();

    // ============ Phase C: pool-1 scores ====================================
    {
        const float pw1_l = __ldg(&pw1[lane]);
        const float invn1 = __fdividef(1.f, sm[OFF_RED + 0]);
        for (int i = wid; i < N_; i += NW) {
            float s = warpSum(sm[OFF_HO + i * D1_ + lane] * pw1_l);
            if (lane == 0) sm[OFF_SC + i] = __fdividef(1.f, 1.f + __expf(-s * invn1));
        }
    }
    __syncthreads();

    // stable descending rank == jax.lax.top_k order
    if (tid < N_) {
        const float si = sm[OFF_SC + tid];
        int cnt = 0;
        for (int j = 0; j < N_; j++) {
            const float sj = sm[OFF_SC + j];
            cnt += (sj > si) || (sj == si && j < tid);
        }
        if (cnt < K1_) smi[OFF_PERM + cnt] = tid;
    }
    __syncthreads();

    for (int r = tid; r < K1_; r += NT) {
        float v = sm[OFF_SC + smi[OFF_PERM + r]];
        sm[OFF_VAL + r] = v;
        out[512 * 2 + (size_t)b * K1_ + r] = v;
    }
    __syncthreads();

    // gated xk = hout[perm] * vals  (into dead h1 region)
    for (int t = tid; t < K1_ * D1_; t += NT) {
        const int r = t >> 5, d = t & 31;
        sm[OFF_H + t] = sm[OFF_HO + smi[OFF_PERM + r] * D1_ + d] * sm[OFF_VAL + r];
    }
    __syncthreads();

    // x1 readout partials (warps 0-3)
    if (wid < 4) {
        float mx = -INFINITY, s = 0.f;
        for (int r = wid * 25; r < wid * 25 + 25; r++) {
            float v = sm[OFF_H + r * D1_ + lane];
            mx = fmaxf(mx, v);
            s += v;
        }
        sm[OFF_AL + (wid * 2 + 0) * 32 + lane] = mx;
        sm[OFF_AL + (wid * 2 + 1) * 32 + lane] = s;
    }
    // AKB via warp ballot: lane = pooled column
    for (int r = wid; r < K1_; r += NW) {
        const int pr = smi[OFF_PERM + r];
        const unsigned* arow = smu + OFF_ADJB + pr * 7;
        #pragma unroll
        for (int w = 0; w < 4; w++) {
            const int c = w * 32 + lane;
            bool bit = false;
            if (c < K1_) {
                const int pc = smi[OFF_PERM + c];
                bit = (arow[pc >> 5] >> (pc & 31)) & 1u;
            }
            unsigned bal = __ballot_sync(0xffffffffu, bit);
            if (lane == 0) smu[OFF_AKB + r * 4 + w] = bal;
        }
    }
    __syncthreads();   // ADJB dead from here

    // combine x1 partials; a2 = ak | (ak_nz @ ak_nz); stage W2 into ADJB
    if (tid < 32) {
        float mx = fmaxf(fmaxf(sm[OFF_AL + 0 * 32 + lane], sm[OFF_AL + 2 * 32 + lane]),
                         fmaxf(sm[OFF_AL + 4 * 32 + lane], sm[OFF_AL + 6 * 32 + lane]));
        float s = sm[OFF_AL + 1 * 32 + lane] + sm[OFF_AL + 3 * 32 + lane]
                + sm[OFF_AL + 5 * 32 + lane] + sm[OFF_AL + 7 * 32 + lane];
        sm[OFF_Z + lane]      = mx;
        sm[OFF_Z + 32 + lane] = s * (1.f / K1_);
    }
    for (int t = tid; t < K1_ * 4; t += NT) {
        const int r = t >> 2, w = t & 3;
        unsigned acc = smu[OFF_AKB + t];
        #pragma unroll
        for (int kc = 0; kc < 4; kc++) {
            unsigned rw = smu[OFF_AKB + r * 4 + kc];
            while (rw) {
                const int k = __ffs(rw) - 1; rw &= rw - 1;
                acc |= smu[OFF_AKB + (kc * 32 + k) * 4 + w];
            }
        }
        smu[OFF_A2B + t] = acc;
    }
    for (int t = tid; t < D1_ * D2_; t += NT) sm[OFF_ADJB + t] = W2[t];
    __syncthreads();

    // ============ Phase E: GAT2 =============================================
    const float a2s_l = __ldg(&a2s[lane]);
    const float a2d_l = __ldg(&a2d[lane]);
    const float b2_l  = __ldg(&b2[lane]);
    float* sXK   = sm + OFF_H;                 // [100x32]
    float* sH2   = sm + OFF_HO;                // [100x32]
    float* sOUT2 = sm + OFF_HO + K1_ * D2_;    // [100x32]
    float* sW2   = sm + OFF_ADJB;              // [32x32]
    float* sAL2  = sm + OFF_AL;                // [16 x ALP] alpha scratch

    for (int i = wid; i < K1_; i += NW) {
        const float4* xr4 = (const float4*)(sXK + i * D1_);
        float acc = 0.f;
        #pragma unroll
        for (int k4 = 0; k4 < D1_ / 4; k4++) {
            float4 xv = xr4[k4];
            const int k = k4 * 4;
            acc = fmaf(xv.x, sW2[(k + 0) * D2_ + lane], acc);
            acc = fmaf(xv.y, sW2[(k + 1) * D2_ + lane], acc);
            acc = fmaf(xv.z, sW2[(k + 2) * D2_ + lane], acc);
            acc = fmaf(xv.w, sW2[(k + 3) * D2_ + lane], acc);
        }
        sH2[i * D2_ + lane] = acc;
        float es = warpSum(acc * a2s_l);
        float ed = warpSum(acc * a2d_l);
        if (lane == 0) { sm[OFF_ES + i] = es; sm[OFF_ED + i] = ed; }
    }
    __syncthreads();

    // GAT2 attention + aggregation: 2 rows per warp
    for (int g = wid; g < K1_ / 2; g += NW) {
        const int i0 = 2 * g, i1 = i0 + 1;
        const float ed0 = sm[OFF_ED + i0];
        const float ed1 = sm[OFF_ED + i1];
        float* al2 = sAL2 + wid * ALP;
        float alr0[4], alr1[4];
        float mx0 = -INFINITY, mx1 = -INFINITY;
        #pragma unroll
        for (int c = 0; c < 4; c++) {
            const int j = c * 32 + lane;
            float lg0 = NEGF, lg1 = NEGF;
            if (j < K1_) {
                const float esj = sm[OFF_ES + j];
                const unsigned b0 = smu[OFF_A2B + i0 * 4 + c];
                const unsigned b1w = smu[OFF_A2B + i1 * 4 + c];
                if ((j == i0) || ((b0 >> lane) & 1u))  lg0 = lrelu02(ed0 + esj);
                if ((j == i1) || ((b1w >> lane) & 1u)) lg1 = lrelu02(ed1 + esj);
            }
            alr0[c] = lg0; alr1[c] = lg1;
            mx0 = fmaxf(mx0, lg0); mx1 = fmaxf(mx1, lg1);
        }
        mx0 = warpMax(mx0); mx1 = warpMax(mx1);
        float s0 = 0.f, s1 = 0.f;
        #pragma unroll
        for (int c = 0; c < 4; c++) {
            const int j = c * 32 + lane;
            if (j < K1_) {
                float e0 = __expf(alr0[c] - mx0);
                float e1 = __expf(alr1[c] - mx1);
                al2[j] = e0;
                al2[100 + j] = e1;
                s0 += e0; s1 += e1;
            }
        }
        s0 = warpSum(s0); s1 = warpSum(s1);
        const float inv0 = __fdividef(1.f, s0);
        const float inv1 = __fdividef(1.f, s1);

        const float4* a40 = (const float4*)al2;
        const float4* a41 = (const float4*)(al2 + 100);
        float p00 = 0.f, p01 = 0.f, p02 = 0.f, p03 = 0.f;
        float p10 = 0.f, p11 = 0.f, p12 = 0.f, p13 = 0.f;
        #pragma unroll 5
        for (int j4 = 0; j4 < K1_ / 4; j4++) {
            float4 a0 = a40[j4];
            float4 a1 = a41[j4];
            const int j = j4 * 4;
            float h0 = sH2[(j + 0) * D2_ + lane];
            float h1 = sH2[(j + 1) * D2_ + lane];
            float h2 = sH2[(j + 2) * D2_ + lane];
            float h3 = sH2[(j + 3) * D2_ + lane];
            p00 = fmaf(a0.x, h0, p00); p01 = fmaf(a0.y, h1, p01);
            p02 = fmaf(a0.z, h2, p02); p03 = fmaf(a0.w, h3, p03);
            p10 = fmaf(a1.x, h0, p10); p11 = fmaf(a1.y, h1, p11);
            p12 = fmaf(a1.z, h2, p12); p13 = fmaf(a1.w, h3, p13);
        }
        sOUT2[i0 * D2_ + lane] = ((p00 + p01) + (p02 + p03)) * inv0 + b2_l;
        sOUT2[i1 * D2_ + lane] = ((p10 + p11) + (p12 + p13)) * inv1 + b2_l;
    }
    __syncthreads();

    // ============ Phase F: pool-2 ===========================================
    {
        const float pw2_l = __ldg(&pw2[lane]);
        const float invn2 = __fdividef(1.f, sm[OFF_RED + 1]);
        for (int i = wid; i < K1_; i += NW) {
            float s = warpSum(sOUT2[i * D2_ + lane] * pw2_l);
            if (lane == 0) sm[OFF_SC + i] = __fdividef(1.f, 1.f + __expf(-s * invn2));
        }
    }
    __syncthreads();

    if (tid < K1_) {
        const float si = sm[OFF_SC + tid];
        int cnt = 0;
        for (int j = 0; j < K1_; j++) {
            const float sj = sm[OFF_SC + j];
            cnt += (sj > si) || (sj == si && j < tid);
        }
        if (cnt < K2_) smi[OFF_PERM2 + cnt] = tid;
    }
    __syncthreads();

    for (int r = tid; r < K2_; r += NT) {
        float v = sm[OFF_SC + smi[OFF_PERM2 + r]];
        sm[OFF_VAL + r] = v;
        out[512 * 2 + 512 * K1_ + (size_t)b * K2_ + r] = v;
    }
    __syncthreads();

    float* sXK2 = sm + OFF_H + K1_ * D1_;   // [50x32]
    for (int t = tid; t < K2_ * D2_; t += NT) {
        const int r = t >> 5, d = t & 31;
        sXK2[t] = sOUT2[smi[OFF_PERM2 + r] * D2_ + d] * sm[OFF_VAL + r];
    }
    __syncthreads();

    // x2 readout partials (warps 0-1)
    if (wid < 2) {
        float mx = -INFINITY, s = 0.f;
        for (int r = wid * 25; r < wid * 25 + 25; r++) {
            float v = sXK2[r * D2_ + lane];
            mx = fmaxf(mx, v);
            s += v;
        }
        sm[OFF_AL + (wid * 2 + 0) * 32 + lane] = mx;
        sm[OFF_AL + (wid * 2 + 1) * 32 + lane] = s;
    }
    __syncthreads();
    if (tid < 32) {
        float mx = fmaxf(sm[OFF_AL + 0 * 32 + lane], sm[OFF_AL + 2 * 32 + lane]);
        float s  = sm[OFF_AL + 1 * 32 + lane] + sm[OFF_AL + 3 * 32 + lane];
        sm[OFF_Z + 64 + lane] = mx;
        sm[OFF_Z + 96 + lane] = s * (1.f / K2_);
    }
    __syncthreads();

    // ============ Phase G: MLP head (warp 0) ================================
    if (wid == 0) {
        const float invbn = 1.0f / sqrtf(1.0f + 1e-5f);
        float acc = __ldg(&fc1_b[lane]);
        #pragma unroll 4
        for (int k = 0; k < 128; k++) acc = fmaf(sm[OFF_Z + k], __ldg(&fc1_w[k * 32 + lane]), acc);
        acc = fmaxf(acc, 0.f);
        sm[OFF_Z + 128 + lane] = __ldg(&bn4_g[lane]) * acc * invbn + __ldg(&bn4_b[lane]);
        __syncwarp();
        if (lane < 8) {
            float a = __ldg(&fc2_b[lane]);
            #pragma unroll
            for (int k = 0; k < 32; k++) a = fmaf(sm[OFF_Z + 128 + k], __ldg(&fc2_w[k * 8 + lane]), a);
            a = fmaxf(a, 0.f);
            sm[OFF_Z + 160 + lane] = __ldg(&bn5_g[lane]) * a * invbn + __ldg(&bn5_b[lane]);
        }
        __syncwarp();
        if (lane < 2) {
            float a = __ldg(&fc3_b[lane]);
            #pragma unroll
            for (int k = 0; k < 8; k++) a = fmaf(sm[OFF_Z + 160 + k], __ldg(&fc3_w[k * 2 + lane]), a);
            sm[OFF_Z + 170 + lane] = a;
        }
        __syncwarp();
        if (lane == 0) {
            float l0 = sm[OFF_Z + 170], l1 = sm[OFF_Z + 171];
            float m = fmaxf(l0, l1);
            float lse = m + __logf(__expf(l0 - m) + __expf(l1 - m));
            out[(size_t)b * 2 + 0] = l0 - lse;
            out[(size_t)b * 2 + 1] = l1 - lse;
        }
    }
}

extern "C" void kernel_launch(void* const* d_in, const int* in_sizes, int n_in,
                              void* d_out, int out_size) {
    const float* x     = (const float*)d_in[0];
    const float* adj   = (const float*)d_in[1];
    const float* W1    = (const float*)d_in[2];
    const float* a1s   = (const float*)d_in[3];
    const float* a1d   = (const float*)d_in[4];
    const float* b1    = (const float*)d_in[5];
    const float* W2    = (const float*)d_in[6];
    const float* a2s   = (const float*)d_in[7];
    const float* a2d   = (const float*)d_in[8];
    const float* b2    = (const float*)d_in[9];
    const float* pw1   = (const float*)d_in[10];
    const float* pw2   = (const float*)d_in[11];
    const float* fc1w  = (const float*)d_in[12];
    const float* fc1b  = (const float*)d_in[13];
    const float* fc2w  = (const float*)d_in[14];
    const float* fc2b  = (const float*)d_in[15];
    const float* fc3w  = (const float*)d_in[16];
    const float* fc3b  = (const float*)d_in[17];
    const float* bn4g  = (const float*)d_in[18];
    const float* bn4b  = (const float*)d_in[19];
    const float* bn5g  = (const float*)d_in[20];
    const float* bn5b  = (const float*)d_in[21];
    float* out = (float*)d_out;

    k_pre<<<B_ + B_ * 5, 256>>>(x, adj, W1, a1s, a1d);

    const int smem_bytes = SMEM_FLOATS * (int)sizeof(float);
    cudaFuncSetAttribute(nngat_main, cudaFuncAttributeMaxDynamicSharedMemorySize,
                         smem_bytes);
    nngat_main<<<B_, NT, smem_bytes>>>(
        W2, a2s, a2d, b1, b2, pw1, pw2,
        fc1w, fc1b, fc2w, fc2b, fc3w, fc3b, bn4g, bn4b, bn5g, bn5b, out);
}